// round 4
// baseline (speedup 1.0000x reference)
#include <cuda_runtime.h>
#include <cuda_fp16.h>
#include <math.h>
#include <stdint.h>

#define BATCH   128
#define EMBED   512
#define HIDDEN  512
#define VOCAB   32000
#define TSTEPS  20
#define NVBLK   (VOCAB/128)   // 250 logits blocks

// ---------------------------------------------------------------------------
// Persistent device scratch (re-written every launch -> deterministic)
__device__ float  g_xh[BATCH * 1024];      // [b][0:512]=x, [b][512:1024]=h (fp32)
__device__ float  g_c[BATCH * HIDDEN];
__device__ float  g_gates[BATCH * 2048];
__device__ float  g_pval[NVBLK * BATCH];   // per-CTA column max of approx logits
__device__ float  g_logits[(size_t)BATCH * VOCAB];  // approx logits [b][v] (16.4MB)
__device__ __half g_W1[VOCAB * 512];       // fp16(W_fc)
__device__ __half g_h1[BATCH * 512];       // fp16(h)

__device__ __forceinline__ float sigf(float x) { return 1.0f / (1.0f + expf(-x)); }

// ---------------------------------------------------------------------------
__device__ __forceinline__ uint32_t smem_u32(const void* p) {
    uint32_t a;
    asm("{ .reg .u64 t; cvta.to.shared.u64 t, %1; cvt.u32.u64 %0, t; }" : "=r"(a) : "l"(p));
    return a;
}
__device__ __forceinline__ void cp16(uint32_t dst, const void* src) {
    asm volatile("cp.async.cg.shared.global [%0], [%1], 16;" :: "r"(dst), "l"(src) : "memory");
}
#define CP_COMMIT() asm volatile("cp.async.commit_group;" ::: "memory")
template <int N> __device__ __forceinline__ void cp_wait() {
    asm volatile("cp.async.wait_group %0;" :: "n"(N) : "memory");
}
__device__ __forceinline__ void ldsm4(uint32_t* r, uint32_t a) {
    asm volatile("ldmatrix.sync.aligned.m8n8.x4.shared.b16 {%0,%1,%2,%3}, [%4];"
                 : "=r"(r[0]), "=r"(r[1]), "=r"(r[2]), "=r"(r[3]) : "r"(a));
}
__device__ __forceinline__ void mma16816(float* d, const uint32_t* a, const uint32_t* b) {
    asm volatile(
        "mma.sync.aligned.m16n8k16.row.col.f32.f16.f16.f32 "
        "{%0,%1,%2,%3}, {%4,%5,%6,%7}, {%8,%9}, {%0,%1,%2,%3};"
        : "+f"(d[0]), "+f"(d[1]), "+f"(d[2]), "+f"(d[3])
        : "r"(a[0]), "r"(a[1]), "r"(a[2]), "r"(a[3]), "r"(b[0]), "r"(b[1]));
}

// ---------------------------------------------------------------------------
__global__ void init_kernel(const float* __restrict__ features) {
    int b = blockIdx.x, t = threadIdx.x;
    for (int k = t; k < 512; k += 256) {
        g_xh[b * 1024 + k]       = features[b * 512 + k];
        g_xh[b * 1024 + 512 + k] = 0.0f;
        g_c[b * 512 + k]         = 0.0f;
        g_h1[b * 512 + k]        = __float2half_rn(0.0f);
    }
}

// Convert W_fc -> fp16, once per launch. 4,096,000 float4s.
__global__ void wsplit_kernel(const float* __restrict__ Wfc) {
    size_t i = (size_t)blockIdx.x * blockDim.x + threadIdx.x;
    float4 v = ((const float4*)Wfc)[i];
    __half2* w1 = (__half2*)g_W1;
    w1[i * 2]     = __halves2half2(__float2half_rn(v.x), __float2half_rn(v.y));
    w1[i * 2 + 1] = __halves2half2(__float2half_rn(v.z), __float2half_rn(v.w));
}

// ---------------------------------------------------------------------------
// gates[n][m] = sum_k xh[n][k] * Wcat[m][k] + bias[m]   (fp32)
__global__ __launch_bounds__(128) void gates_kernel(
    const float* __restrict__ Wih, const float* __restrict__ Whh,
    const float* __restrict__ bih, const float* __restrict__ bhh) {
    __shared__ float As[16][65];
    __shared__ float Bs[16][33];
    const int m0 = blockIdx.x * 64;
    const int n0 = blockIdx.y * 32;
    const int tid = threadIdx.x;
    const int lr = tid >> 2;
    const int lc = (tid & 3) * 4;
    const int tr = tid >> 3;
    const int tc = tid & 7;
    float acc[4][4] = {};

    for (int k0 = 0; k0 < 1024; k0 += 16) {
        const float* W = (k0 < 512) ? Wih : Whh;
        const int kc = (k0 < 512) ? k0 : (k0 - 512);
        float4 a0 = *(const float4*)(W + (size_t)(m0 + lr) * 512 + kc + lc);
        float4 a1 = *(const float4*)(W + (size_t)(m0 + 32 + lr) * 512 + kc + lc);
        float4 b0 = *(const float4*)(g_xh + (size_t)(n0 + lr) * 1024 + k0 + lc);
        __syncthreads();
        As[lc + 0][lr] = a0.x; As[lc + 1][lr] = a0.y;
        As[lc + 2][lr] = a0.z; As[lc + 3][lr] = a0.w;
        As[lc + 0][32 + lr] = a1.x; As[lc + 1][32 + lr] = a1.y;
        As[lc + 2][32 + lr] = a1.z; As[lc + 3][32 + lr] = a1.w;
        Bs[lc + 0][lr] = b0.x; Bs[lc + 1][lr] = b0.y;
        Bs[lc + 2][lr] = b0.z; Bs[lc + 3][lr] = b0.w;
        __syncthreads();
#pragma unroll
        for (int kk = 0; kk < 16; ++kk) {
            float av[4], bv[4];
#pragma unroll
            for (int i = 0; i < 4; ++i) av[i] = As[kk][tr * 4 + i];
#pragma unroll
            for (int j = 0; j < 4; ++j) bv[j] = Bs[kk][tc * 4 + j];
#pragma unroll
            for (int i = 0; i < 4; ++i)
#pragma unroll
                for (int j = 0; j < 4; ++j) acc[i][j] = fmaf(av[i], bv[j], acc[i][j]);
        }
    }
#pragma unroll
    for (int i = 0; i < 4; ++i) {
        int m = m0 + tr * 4 + i;
        float bb = bih[m] + bhh[m];
#pragma unroll
        for (int j = 0; j < 4; ++j) {
            int n = n0 + tc * 4 + j;
            g_gates[(size_t)n * 2048 + m] = acc[i][j] + bb;
        }
    }
}

// ---------------------------------------------------------------------------
// LSTM pointwise + fp16 cast of h
__global__ void lstm_pw_kernel() {
    int b = blockIdx.x, j = threadIdx.x;
    const float* g = g_gates + (size_t)b * 2048;
    float ig = sigf(g[j]);
    float fg = sigf(g[512 + j]);
    float gg = tanhf(g[1024 + j]);
    float og = sigf(g[1536 + j]);
    float c = fg * g_c[b * 512 + j] + ig * gg;
    g_c[b * 512 + j] = c;
    float h = og * tanhf(c);
    g_xh[b * 1024 + 512 + j] = h;
    g_h1[b * 512 + j] = __float2half_rn(h);
}

// ---------------------------------------------------------------------------
// HMMA approx logits: per CTA 128 vocab x 128 batch, K=512, single fp16 pass.
// Writes approx logits (with bias) to g_logits[b][v] and per-CTA column maxes.
#define KC      32
#define ROWB    80
#define TILEB   (128 * ROWB)       // 10240
#define STAGEB  (2 * TILEB)        // 20480 (W1 tile + h1 tile)
#define SMEM_LOG (128 * 132 * 4 + 1024)   // epilogue slog + pv (>= 2*STAGEB)

__global__ __launch_bounds__(256, 1) void logits_mma_kernel(const float* __restrict__ bfc) {
    extern __shared__ char smem[];
    const uint32_t sb = smem_u32(smem);
    const int tid = threadIdx.x;
    const int wid = tid >> 5;
    const int lane = tid & 31;
    const int vb = blockIdx.x * 128;
    const int vrow0 = (wid & 1) * 64;
    const int brow0 = (wid >> 1) * 32;

    float d0[4][4][4] = {};

    // ---- stage loader: 1024 granules of 16B, 4 per thread ----
    auto load_stage = [&](int s, int k0) {
        const uint32_t st = sb + s * STAGEB;
        const __half* srcs[2] = { g_W1 + (size_t)vb * 512 + k0, g_h1 + k0 };
#pragma unroll
        for (int i = 0; i < 4; ++i) {
            int lin = i * 256 + tid;
            int t   = lin >> 9;
            int idx = lin & 511;
            int row = idx & 127;
            int col = idx >> 7;          // 0..3 (16B granules)
            cp16(st + t * TILEB + row * ROWB + col * 16,
                 srcs[t] + (size_t)row * 512 + col * 8);
        }
        CP_COMMIT();
    };

    load_stage(0, 0);
    load_stage(1, KC);

    for (int kc = 0; kc < 16; ++kc) {
        if (kc < 15) cp_wait<1>(); else cp_wait<0>();
        __syncthreads();
        const uint32_t st = sb + (kc & 1) * STAGEB;
#pragma unroll
        for (int ks = 0; ks < 2; ++ks) {
            const uint32_t kb = ks * 32;
            uint32_t a1[4][4];
#pragma unroll
            for (int mi = 0; mi < 4; ++mi) {
                const int mat = lane >> 3;
                const uint32_t row = vrow0 + mi * 16 + (mat & 1) * 8 + (lane & 7);
                ldsm4(a1[mi], st + row * ROWB + kb + (mat >> 1) * 16);
            }
            uint32_t b1[4][2];
#pragma unroll
            for (int j = 0; j < 2; ++j) {
                const int mat = lane >> 3;
                const uint32_t row = brow0 + j * 16 + (mat >> 1) * 8 + (lane & 7);
                uint32_t r[4];
                ldsm4(r, st + TILEB + row * ROWB + kb + (mat & 1) * 16);
                b1[2 * j][0] = r[0]; b1[2 * j][1] = r[1];
                b1[2 * j + 1][0] = r[2]; b1[2 * j + 1][1] = r[3];
            }
#pragma unroll
            for (int mi = 0; mi < 4; ++mi)
#pragma unroll
                for (int nf = 0; nf < 4; ++nf)
                    mma16816(d0[mi][nf], a1[mi], b1[nf]);
        }
        __syncthreads();
        if (kc + 2 < 16) load_stage(kc & 1, (kc + 2) * KC);
    }

    // ---- epilogue: logits(+bias) into smem [b][v], column max, global store --
    __syncthreads();
    float* slog = (float*)smem;                         // [128][132]
    float* pv   = (float*)(smem + 128 * 132 * 4);       // [256]
#pragma unroll
    for (int mi = 0; mi < 4; ++mi) {
        const int v0 = vrow0 + mi * 16 + (lane >> 2);
        const int v1 = v0 + 8;
        const float bias0 = bfc[vb + v0];
        const float bias1 = bfc[vb + v1];
#pragma unroll
        for (int nf = 0; nf < 4; ++nf) {
            const int b0 = brow0 + nf * 8 + 2 * (lane & 3);
            slog[(b0)     * 132 + v0] = d0[mi][nf][0] + bias0;
            slog[(b0 + 1) * 132 + v0] = d0[mi][nf][1] + bias0;
            slog[(b0)     * 132 + v1] = d0[mi][nf][2] + bias1;
            slog[(b0 + 1) * 132 + v1] = d0[mi][nf][3] + bias1;
        }
    }
    __syncthreads();
    // per-column (batch) max over the 128 vocab rows of this CTA
    {
        const int c = tid & 127;
        const int hh = tid >> 7;
        const float* col = slog + c * 132 + hh * 64;
        float bv = col[0];
#pragma unroll 8
        for (int v = 1; v < 64; ++v) bv = fmaxf(bv, col[v]);
        pv[tid] = bv;
    }
    // coalesced store of the 128x128 logits tile to g_logits[b][vb..vb+127]
    for (int row = wid; row < 128; row += 8) {
        const float* sr = slog + row * 132 + lane * 4;
        float4 v = make_float4(sr[0], sr[1], sr[2], sr[3]);
        *(float4*)(g_logits + (size_t)row * VOCAB + vb + lane * 4) = v;
    }
    __syncthreads();
    if (tid < 128)
        g_pval[(size_t)blockIdx.x * 128 + tid] = fmaxf(pv[tid], pv[tid + 128]);
}

// ---------------------------------------------------------------------------
// Fused reduce + exact fixup + output + embedding gather. One block per batch b.
__global__ __launch_bounds__(256) void fixup_kernel(
    const float* __restrict__ Wfc, const float* __restrict__ bfc,
    const float* __restrict__ emb, float* __restrict__ out, int step) {
    __shared__ float sh[512];
    __shared__ float sv[256];
    __shared__ int   si[256];
    const int b = blockIdx.x, t = threadIdx.x;

    for (int k = t; k < 512; k += 256) sh[k] = g_xh[b * 1024 + 512 + k];

    // global max of approx logits for this batch row
    float m = -INFINITY;
    for (int i = t; i < NVBLK; i += 256) m = fmaxf(m, g_pval[(size_t)i * 128 + b]);
    sv[t] = m;
    __syncthreads();
    for (int s = 128; s > 0; s >>= 1) {
        if (t < s) sv[t] = fmaxf(sv[t], sv[t + s]);
        __syncthreads();
    }
    const float bmax = sv[0];
    __syncthreads();
    const float thr = bmax - 0.01f * fmaxf(1.0f, fabsf(bmax));

    // scan approx logits; exact fp32 recompute for candidates
    float best = -INFINITY;
    int bi = 0x7fffffff;
    const float* lg = g_logits + (size_t)b * VOCAB;
    for (int v = t; v < VOCAB; v += 256) {
        if (lg[v] >= thr) {
            const float* w = Wfc + (size_t)v * 512;
            float acc = 0.0f;
#pragma unroll 4
            for (int k = 0; k < 512; k += 4) {
                float4 wv = *(const float4*)(w + k);
                acc += wv.x * sh[k] + wv.y * sh[k + 1] + wv.z * sh[k + 2] + wv.w * sh[k + 3];
            }
            acc += bfc[v];
            if (acc > best || (acc == best && v < bi)) { best = acc; bi = v; }
        }
    }
    sv[t] = best; si[t] = bi;
    __syncthreads();
    for (int s = 128; s > 0; s >>= 1) {
        if (t < s) {
            float v = sv[t + s]; int ix = si[t + s];
            if (v > sv[t] || (v == sv[t] && ix < si[t])) { sv[t] = v; si[t] = ix; }
        }
        __syncthreads();
    }
    const int idx = si[0];
    if (t == 0) {
        out[b * TSTEPS + step] = (float)idx;
        out[BATCH * TSTEPS + b * TSTEPS + step] = sv[0];
    }
    for (int k = t; k < 512; k += 256)
        g_xh[b * 1024 + k] = emb[(size_t)idx * 512 + k];
}

// ---------------------------------------------------------------------------
extern "C" void kernel_launch(void* const* d_in, const int* in_sizes, int n_in,
                              void* d_out, int out_size) {
    const float* features = (const float*)d_in[0];
    const float* emb = (const float*)d_in[2];
    const float* Wih = (const float*)d_in[3];
    const float* Whh = (const float*)d_in[4];
    const float* bih = (const float*)d_in[5];
    const float* bhh = (const float*)d_in[6];
    const float* Wfc = (const float*)d_in[7];
    const float* bfc = (const float*)d_in[8];
    float* out = (float*)d_out;

    cudaFuncSetAttribute(logits_mma_kernel,
                         cudaFuncAttributeMaxDynamicSharedMemorySize, SMEM_LOG);

    init_kernel<<<BATCH, 256>>>(features);
    wsplit_kernel<<<16000, 256>>>(Wfc);
    for (int t = 0; t < TSTEPS; ++t) {
        gates_kernel<<<dim3(32, 4), 128>>>(Wih, Whh, bih, bhh);
        lstm_pw_kernel<<<BATCH, 512>>>();
        logits_mma_kernel<<<NVBLK, 256, SMEM_LOG>>>(bfc);
        fixup_kernel<<<BATCH, 256>>>(Wfc, bfc, emb, out, t);
    }
}

// round 5
// speedup vs baseline: 1.2317x; 1.2317x over previous
#include <cuda_runtime.h>
#include <cuda_fp16.h>
#include <math.h>
#include <stdint.h>

#define BATCH   128
#define EMBED   512
#define HIDDEN  512
#define VOCAB   32000
#define TSTEPS  20
#define VTILE   64
#define NVBLK2  (VOCAB/VTILE)   // 500 logits blocks

// ---------------------------------------------------------------------------
// Persistent device scratch (re-written every launch -> deterministic)
__device__ float  g_xh[BATCH * 1024];      // [b][0:512]=x, [b][512:1024]=h (fp32)
__device__ float  g_c[BATCH * HIDDEN];
__device__ float  g_gates[BATCH * 2048];
__device__ float  g_pval[NVBLK2 * BATCH];  // per-CTA column max of approx logits
__device__ __half g_W1[VOCAB * 512];       // fp16(W_fc)
__device__ __half g_h1[BATCH * 512];       // fp16(h)

__device__ __forceinline__ float sigf(float x) { return 1.0f / (1.0f + expf(-x)); }

// ---------------------------------------------------------------------------
__device__ __forceinline__ uint32_t smem_u32(const void* p) {
    uint32_t a;
    asm("{ .reg .u64 t; cvta.to.shared.u64 t, %1; cvt.u32.u64 %0, t; }" : "=r"(a) : "l"(p));
    return a;
}
__device__ __forceinline__ void cp16(uint32_t dst, const void* src) {
    asm volatile("cp.async.cg.shared.global [%0], [%1], 16;" :: "r"(dst), "l"(src) : "memory");
}
#define CP_COMMIT() asm volatile("cp.async.commit_group;" ::: "memory")
template <int N> __device__ __forceinline__ void cp_wait() {
    asm volatile("cp.async.wait_group %0;" :: "n"(N) : "memory");
}
__device__ __forceinline__ void ldsm4(uint32_t* r, uint32_t a) {
    asm volatile("ldmatrix.sync.aligned.m8n8.x4.shared.b16 {%0,%1,%2,%3}, [%4];"
                 : "=r"(r[0]), "=r"(r[1]), "=r"(r[2]), "=r"(r[3]) : "r"(a));
}
__device__ __forceinline__ void mma16816(float* d, const uint32_t* a, const uint32_t* b) {
    asm volatile(
        "mma.sync.aligned.m16n8k16.row.col.f32.f16.f16.f32 "
        "{%0,%1,%2,%3}, {%4,%5,%6,%7}, {%8,%9}, {%0,%1,%2,%3};"
        : "+f"(d[0]), "+f"(d[1]), "+f"(d[2]), "+f"(d[3])
        : "r"(a[0]), "r"(a[1]), "r"(a[2]), "r"(a[3]), "r"(b[0]), "r"(b[1]));
}

// ---------------------------------------------------------------------------
__global__ void init_kernel(const float* __restrict__ features) {
    int b = blockIdx.x, t = threadIdx.x;
    for (int k = t; k < 512; k += 256) {
        g_xh[b * 1024 + k]       = features[b * 512 + k];
        g_xh[b * 1024 + 512 + k] = 0.0f;
        g_c[b * 512 + k]         = 0.0f;
        g_h1[b * 512 + k]        = __float2half_rn(0.0f);
    }
}

// Convert W_fc -> fp16, once per launch. 4,096,000 float4s.
__global__ void wsplit_kernel(const float* __restrict__ Wfc) {
    size_t i = (size_t)blockIdx.x * blockDim.x + threadIdx.x;
    float4 v = ((const float4*)Wfc)[i];
    __half2* w1 = (__half2*)g_W1;
    w1[i * 2]     = __halves2half2(__float2half_rn(v.x), __float2half_rn(v.y));
    w1[i * 2 + 1] = __halves2half2(__float2half_rn(v.z), __float2half_rn(v.w));
}

// ---------------------------------------------------------------------------
// gates[n][m] = sum_k xh[n][k] * Wcat[m][k] + bias[m]   (fp32)
__global__ __launch_bounds__(128) void gates_kernel(
    const float* __restrict__ Wih, const float* __restrict__ Whh,
    const float* __restrict__ bih, const float* __restrict__ bhh) {
    __shared__ float As[16][65];
    __shared__ float Bs[16][33];
    const int m0 = blockIdx.x * 64;
    const int n0 = blockIdx.y * 32;
    const int tid = threadIdx.x;
    const int lr = tid >> 2;
    const int lc = (tid & 3) * 4;
    const int tr = tid >> 3;
    const int tc = tid & 7;
    float acc[4][4] = {};

    for (int k0 = 0; k0 < 1024; k0 += 16) {
        const float* W = (k0 < 512) ? Wih : Whh;
        const int kc = (k0 < 512) ? k0 : (k0 - 512);
        float4 a0 = *(const float4*)(W + (size_t)(m0 + lr) * 512 + kc + lc);
        float4 a1 = *(const float4*)(W + (size_t)(m0 + 32 + lr) * 512 + kc + lc);
        float4 b0 = *(const float4*)(g_xh + (size_t)(n0 + lr) * 1024 + k0 + lc);
        __syncthreads();
        As[lc + 0][lr] = a0.x; As[lc + 1][lr] = a0.y;
        As[lc + 2][lr] = a0.z; As[lc + 3][lr] = a0.w;
        As[lc + 0][32 + lr] = a1.x; As[lc + 1][32 + lr] = a1.y;
        As[lc + 2][32 + lr] = a1.z; As[lc + 3][32 + lr] = a1.w;
        Bs[lc + 0][lr] = b0.x; Bs[lc + 1][lr] = b0.y;
        Bs[lc + 2][lr] = b0.z; Bs[lc + 3][lr] = b0.w;
        __syncthreads();
#pragma unroll
        for (int kk = 0; kk < 16; ++kk) {
            float av[4], bv[4];
#pragma unroll
            for (int i = 0; i < 4; ++i) av[i] = As[kk][tr * 4 + i];
#pragma unroll
            for (int j = 0; j < 4; ++j) bv[j] = Bs[kk][tc * 4 + j];
#pragma unroll
            for (int i = 0; i < 4; ++i)
#pragma unroll
                for (int j = 0; j < 4; ++j) acc[i][j] = fmaf(av[i], bv[j], acc[i][j]);
        }
    }
#pragma unroll
    for (int i = 0; i < 4; ++i) {
        int m = m0 + tr * 4 + i;
        float bb = bih[m] + bhh[m];
#pragma unroll
        for (int j = 0; j < 4; ++j) {
            int n = n0 + tc * 4 + j;
            g_gates[(size_t)n * 2048 + m] = acc[i][j] + bb;
        }
    }
}

// ---------------------------------------------------------------------------
// LSTM pointwise + fp16 cast of h
__global__ void lstm_pw_kernel() {
    int b = blockIdx.x, j = threadIdx.x;
    const float* g = g_gates + (size_t)b * 2048;
    float ig = sigf(g[j]);
    float fg = sigf(g[512 + j]);
    float gg = tanhf(g[1024 + j]);
    float og = sigf(g[1536 + j]);
    float c = fg * g_c[b * 512 + j] + ig * gg;
    g_c[b * 512 + j] = c;
    float h = og * tanhf(c);
    g_xh[b * 1024 + 512 + j] = h;
    g_h1[b * 512 + j] = __float2half_rn(h);
}

// ---------------------------------------------------------------------------
// HMMA approx logits: per CTA 64 vocab x 128 batch, K=512, single fp16 pass.
// 8 warps: warp tile 16 vocab x 64 batch. Writes per-CTA column maxes only.
#define KC      64
#define ROWB    144                 // 64 halves (128B) + 16B pad, conflict-free
#define WTILEB  (VTILE * ROWB)      // 9216
#define HTILEB  (128 * ROWB)        // 18432
#define STAGEB  (WTILEB + HTILEB)   // 27648
#define SMEM_LOG (2 * STAGEB)       // 55296 (epilogue slog 34816 reuses it)

__global__ __launch_bounds__(256, 2) void logits_mma_kernel(const float* __restrict__ bfc) {
    extern __shared__ char smem[];
    __shared__ float pv[256];
    const uint32_t sb = smem_u32(smem);
    const int tid = threadIdx.x;
    const int wid = tid >> 5;
    const int lane = tid & 31;
    const int vb = blockIdx.x * VTILE;
    const int vrow0 = (wid & 3) * 16;
    const int brow0 = (wid >> 2) * 64;

    float d0[8][4] = {};

    // stage loader: 512 W-granules + 1024 h-granules of 16B; 6 per thread
    auto load_stage = [&](int s, int k0) {
        const uint32_t st = sb + s * STAGEB;
#pragma unroll
        for (int i = 0; i < 6; ++i) {
            int lin = i * 256 + tid;
            if (lin < 512) {
                int row = lin >> 3, col = lin & 7;
                cp16(st + row * ROWB + col * 16,
                     g_W1 + (size_t)(vb + row) * 512 + k0 + col * 8);
            } else {
                int idx = lin - 512;
                int row = idx >> 3, col = idx & 7;
                cp16(st + WTILEB + row * ROWB + col * 16,
                     g_h1 + (size_t)row * 512 + k0 + col * 8);
            }
        }
        CP_COMMIT();
    };

    load_stage(0, 0);
    load_stage(1, KC);

    for (int kc = 0; kc < 8; ++kc) {
        if (kc < 7) cp_wait<1>(); else cp_wait<0>();
        __syncthreads();
        const uint32_t st = sb + (kc & 1) * STAGEB;
#pragma unroll
        for (int ks = 0; ks < 4; ++ks) {
            const uint32_t kb = ks * 32;
            const int mat = lane >> 3;
            uint32_t a1[4];
            {
                const uint32_t row = vrow0 + (mat & 1) * 8 + (lane & 7);
                ldsm4(a1, st + row * ROWB + kb + (mat >> 1) * 16);
            }
            uint32_t b1[8][2];
#pragma unroll
            for (int j = 0; j < 4; ++j) {
                const uint32_t row = brow0 + j * 16 + (mat >> 1) * 8 + (lane & 7);
                uint32_t r[4];
                ldsm4(r, st + WTILEB + row * ROWB + kb + (mat & 1) * 16);
                b1[2 * j][0] = r[0]; b1[2 * j][1] = r[1];
                b1[2 * j + 1][0] = r[2]; b1[2 * j + 1][1] = r[3];
            }
#pragma unroll
            for (int nf = 0; nf < 8; ++nf)
                mma16816(d0[nf], a1, b1[nf]);
        }
        __syncthreads();
        if (kc + 2 < 8) load_stage(kc & 1, (kc + 2) * KC);
    }

    // ---- epilogue: logits(+bias) into smem [b][64], per-column max ----
    __syncthreads();
    float* slog = (float*)smem;            // [128][68]
    const int vloc0 = vrow0 + (lane >> 2);
    const float bias0 = bfc[vb + vloc0];
    const float bias1 = bfc[vb + vloc0 + 8];
#pragma unroll
    for (int nf = 0; nf < 8; ++nf) {
        const int b0 = brow0 + nf * 8 + 2 * (lane & 3);
        slog[(b0)     * 68 + vloc0]     = d0[nf][0] + bias0;
        slog[(b0 + 1) * 68 + vloc0]     = d0[nf][1] + bias0;
        slog[(b0)     * 68 + vloc0 + 8] = d0[nf][2] + bias1;
        slog[(b0 + 1) * 68 + vloc0 + 8] = d0[nf][3] + bias1;
    }
    __syncthreads();
    {
        const int c = tid & 127;
        const int half = tid >> 7;
        const float* col = slog + c * 68 + half * 32;
        float m = col[0];
#pragma unroll 8
        for (int v = 1; v < 32; ++v) m = fmaxf(m, col[v]);
        pv[tid] = m;
    }
    __syncthreads();
    if (tid < 128)
        g_pval[(size_t)blockIdx.x * 128 + tid] = fmaxf(pv[tid], pv[tid + 128]);
}

// ---------------------------------------------------------------------------
// Fused: global max over CTA maxes -> threshold -> exact fp32 recompute of the
// candidate CTA row-blocks -> exact argmax/val -> output + embedding gather.
__global__ __launch_bounds__(256) void fixup_kernel(
    const float* __restrict__ Wfc, const float* __restrict__ bfc,
    const float* __restrict__ emb, float* __restrict__ out, int step) {
    __shared__ float sh[512];
    __shared__ float sv[256];
    __shared__ int   si[256];
    __shared__ int   cand[64];
    __shared__ int   ncand;
    const int b = blockIdx.x, t = threadIdx.x;
    const int wid = t >> 5, lane = t & 31;

    for (int k = t; k < 512; k += 256) sh[k] = g_xh[b * 1024 + 512 + k];
    if (t == 0) ncand = 0;

    // global max of per-CTA column maxes
    float m = -INFINITY;
    for (int c = t; c < NVBLK2; c += 256) m = fmaxf(m, g_pval[(size_t)c * 128 + b]);
    sv[t] = m;
    __syncthreads();
    for (int s = 128; s > 0; s >>= 1) {
        if (t < s) sv[t] = fmaxf(sv[t], sv[t + s]);
        __syncthreads();
    }
    const float gmax = sv[0];
    __syncthreads();
    const float thr = gmax - 0.01f * fmaxf(1.0f, fabsf(gmax));

    // collect candidate CTA blocks
    for (int c = t; c < NVBLK2; c += 256)
        if (g_pval[(size_t)c * 128 + b] >= thr) {
            int p = atomicAdd(&ncand, 1);
            if (p < 64) cand[p] = c;
        }
    __syncthreads();
    const int nc = min(ncand, 64);

    // exact fp32 dots for candidate row-blocks (warp per row, lanes split K)
    float best = -INFINITY;
    int bi = 0x7fffffff;
    for (int ci = 0; ci < nc; ++ci) {
        const int c = cand[ci];
        for (int r = wid; r < VTILE; r += 8) {
            const int v = c * VTILE + r;
            const float* w = Wfc + (size_t)v * 512;
            float acc = 0.0f;
#pragma unroll
            for (int j = 0; j < 4; ++j) {
                float4 wv = *(const float4*)(w + lane * 16 + j * 4);
                const float* hh = sh + lane * 16 + j * 4;
                acc += wv.x * hh[0] + wv.y * hh[1] + wv.z * hh[2] + wv.w * hh[3];
            }
#pragma unroll
            for (int o = 16; o; o >>= 1) acc += __shfl_xor_sync(0xffffffffu, acc, o);
            acc += bfc[v];
            if (lane == 0) {
                if (acc > best || (acc == best && v < bi)) { best = acc; bi = v; }
            }
        }
    }
    sv[t] = (lane == 0) ? best : -INFINITY;
    si[t] = (lane == 0) ? bi : 0x7fffffff;
    __syncthreads();
    for (int s = 128; s > 0; s >>= 1) {
        if (t < s) {
            float v = sv[t + s]; int ix = si[t + s];
            if (v > sv[t] || (v == sv[t] && ix < si[t])) { sv[t] = v; si[t] = ix; }
        }
        __syncthreads();
    }
    const int idx = si[0];
    if (t == 0) {
        out[b * TSTEPS + step] = (float)idx;
        out[BATCH * TSTEPS + b * TSTEPS + step] = sv[0];
    }
    for (int k = t; k < 512; k += 256)
        g_xh[b * 1024 + k] = emb[(size_t)idx * 512 + k];
}

// ---------------------------------------------------------------------------
extern "C" void kernel_launch(void* const* d_in, const int* in_sizes, int n_in,
                              void* d_out, int out_size) {
    const float* features = (const float*)d_in[0];
    const float* emb = (const float*)d_in[2];
    const float* Wih = (const float*)d_in[3];
    const float* Whh = (const float*)d_in[4];
    const float* bih = (const float*)d_in[5];
    const float* bhh = (const float*)d_in[6];
    const float* Wfc = (const float*)d_in[7];
    const float* bfc = (const float*)d_in[8];
    float* out = (float*)d_out;

    cudaFuncSetAttribute(logits_mma_kernel,
                         cudaFuncAttributeMaxDynamicSharedMemorySize, SMEM_LOG);

    init_kernel<<<BATCH, 256>>>(features);
    wsplit_kernel<<<16000, 256>>>(Wfc);
    for (int t = 0; t < TSTEPS; ++t) {
        gates_kernel<<<dim3(32, 4), 128>>>(Wih, Whh, bih, bhh);
        lstm_pw_kernel<<<BATCH, 512>>>();
        logits_mma_kernel<<<NVBLK2, 256, SMEM_LOG>>>(bfc);
        fixup_kernel<<<BATCH, 256>>>(Wfc, bfc, emb, out, t);
    }
}

// round 7
// speedup vs baseline: 1.2550x; 1.0189x over previous
#include <cuda_runtime.h>
#include <cuda_fp16.h>
#include <math.h>
#include <stdint.h>

#define BATCH   128
#define EMBED   512
#define HIDDEN  512
#define VOCAB   32000
#define TSTEPS  20
#define VTILE   64
#define NVBLK2  (VOCAB/VTILE)   // 500 logits blocks

// ---------------------------------------------------------------------------
// Persistent device scratch (re-written every launch -> deterministic)
__device__ float  g_xh[BATCH * 1024];      // [b][0:512]=x, [b][512:1024]=h (fp32)
__device__ float  g_hnew[BATCH * HIDDEN];  // freshly produced h (committed by fixup)
__device__ float  g_c[BATCH * HIDDEN];
__device__ float  g_pval[NVBLK2 * BATCH];  // per-CTA column max of approx logits
__device__ __half g_W1[VOCAB * 512];       // fp16(W_fc)
__device__ __half g_h1[BATCH * 512];       // fp16(h)

__device__ __forceinline__ float sigf(float x) { return 1.0f / (1.0f + expf(-x)); }

// ---------------------------------------------------------------------------
__device__ __forceinline__ uint32_t smem_u32(const void* p) {
    uint32_t a;
    asm("{ .reg .u64 t; cvta.to.shared.u64 t, %1; cvt.u32.u64 %0, t; }" : "=r"(a) : "l"(p));
    return a;
}
__device__ __forceinline__ void cp16(uint32_t dst, const void* src) {
    asm volatile("cp.async.cg.shared.global [%0], [%1], 16;" :: "r"(dst), "l"(src) : "memory");
}
#define CP_COMMIT() asm volatile("cp.async.commit_group;" ::: "memory")
template <int N> __device__ __forceinline__ void cp_wait() {
    asm volatile("cp.async.wait_group %0;" :: "n"(N) : "memory");
}
__device__ __forceinline__ void ldsm4(uint32_t* r, uint32_t a) {
    asm volatile("ldmatrix.sync.aligned.m8n8.x4.shared.b16 {%0,%1,%2,%3}, [%4];"
                 : "=r"(r[0]), "=r"(r[1]), "=r"(r[2]), "=r"(r[3]) : "r"(a));
}
__device__ __forceinline__ void mma16816(float* d, const uint32_t* a, const uint32_t* b) {
    asm volatile(
        "mma.sync.aligned.m16n8k16.row.col.f32.f16.f16.f32 "
        "{%0,%1,%2,%3}, {%4,%5,%6,%7}, {%8,%9}, {%0,%1,%2,%3};"
        : "+f"(d[0]), "+f"(d[1]), "+f"(d[2]), "+f"(d[3])
        : "r"(a[0]), "r"(a[1]), "r"(a[2]), "r"(a[3]), "r"(b[0]), "r"(b[1]));
}

// ---------------------------------------------------------------------------
__global__ void init_kernel(const float* __restrict__ features) {
    int b = blockIdx.x, t = threadIdx.x;
    for (int k = t; k < 512; k += 256) {
        g_xh[b * 1024 + k]       = features[b * 512 + k];
        g_xh[b * 1024 + 512 + k] = 0.0f;
        g_hnew[b * 512 + k]      = 0.0f;
        g_c[b * 512 + k]         = 0.0f;
        g_h1[b * 512 + k]        = __float2half_rn(0.0f);
    }
}

// Convert W_fc -> fp16, once per launch. 4,096,000 float4s.
__global__ void wsplit_kernel(const float* __restrict__ Wfc) {
    size_t i = (size_t)blockIdx.x * blockDim.x + threadIdx.x;
    float4 v = ((const float4*)Wfc)[i];
    __half2* w1 = (__half2*)g_W1;
    w1[i * 2]     = __halves2half2(__float2half_rn(v.x), __float2half_rn(v.y));
    w1[i * 2 + 1] = __halves2half2(__float2half_rn(v.z), __float2half_rn(v.w));
}

// ---------------------------------------------------------------------------
// Fused gates + LSTM pointwise. Reads OLD h from g_xh; writes new h ONLY to
// g_hnew / g_h1 (g_xh h-half is committed later by fixup -> no intra-kernel race).
__global__ __launch_bounds__(128) void gates_pw_kernel(
    const float* __restrict__ Wih, const float* __restrict__ Whh,
    const float* __restrict__ bih, const float* __restrict__ bhh) {
    __shared__ float As[16][68];
    __shared__ float Bs[16][36];
    __shared__ float sg[64][33];
    const int j0 = blockIdx.x * 16;
    const int n0 = blockIdx.y * 32;
    const int tid = threadIdx.x;
    const int lr = tid >> 2;            // 0..31
    const int lc = (tid & 3) * 4;       // 0,4,8,12
    const int tr = tid >> 3;            // 0..15 -> 4 rows each (of 64)
    const int tc = tid & 7;             // 0..7  -> 4 batch cols each
    float acc[4][4] = {};

    for (int k0 = 0; k0 < 1024; k0 += 16) {
        const float* W = (k0 < 512) ? Wih : Whh;
        const int kc = (k0 < 512) ? k0 : (k0 - 512);
        const int r0 = lr,      m0 = (r0 >> 4) * 512 + j0 + (r0 & 15);
        const int r1 = lr + 32, m1 = (r1 >> 4) * 512 + j0 + (r1 & 15);
        float4 a0 = *(const float4*)(W + (size_t)m0 * 512 + kc + lc);
        float4 a1 = *(const float4*)(W + (size_t)m1 * 512 + kc + lc);
        float4 b0 = *(const float4*)(g_xh + (size_t)(n0 + lr) * 1024 + k0 + lc);
        __syncthreads();
        As[lc + 0][r0] = a0.x; As[lc + 1][r0] = a0.y;
        As[lc + 2][r0] = a0.z; As[lc + 3][r0] = a0.w;
        As[lc + 0][r1] = a1.x; As[lc + 1][r1] = a1.y;
        As[lc + 2][r1] = a1.z; As[lc + 3][r1] = a1.w;
        Bs[lc + 0][lr] = b0.x; Bs[lc + 1][lr] = b0.y;
        Bs[lc + 2][lr] = b0.z; Bs[lc + 3][lr] = b0.w;
        __syncthreads();
#pragma unroll
        for (int kk = 0; kk < 16; ++kk) {
            float av[4], bv[4];
#pragma unroll
            for (int i = 0; i < 4; ++i) av[i] = As[kk][tr * 4 + i];
#pragma unroll
            for (int j = 0; j < 4; ++j) bv[j] = Bs[kk][tc * 4 + j];
#pragma unroll
            for (int i = 0; i < 4; ++i)
#pragma unroll
                for (int j = 0; j < 4; ++j) acc[i][j] = fmaf(av[i], bv[j], acc[i][j]);
        }
    }
#pragma unroll
    for (int i = 0; i < 4; ++i) {
        const int row = tr * 4 + i;
        const int m = (row >> 4) * 512 + j0 + (row & 15);
        const float bb = bih[m] + bhh[m];
#pragma unroll
        for (int j = 0; j < 4; ++j)
            sg[row][tc * 4 + j] = acc[i][j] + bb;
    }
    __syncthreads();
#pragma unroll
    for (int q = 0; q < 4; ++q) {
        const int idx = tid * 4 + q;
        const int jl = idx >> 5;
        const int bl = idx & 31;
        const int j = j0 + jl;
        const int b = n0 + bl;
        float ig = sigf(sg[jl][bl]);
        float fg = sigf(sg[16 + jl][bl]);
        float gg = tanhf(sg[32 + jl][bl]);
        float og = sigf(sg[48 + jl][bl]);
        float c = fg * g_c[b * 512 + j] + ig * gg;
        g_c[b * 512 + j] = c;
        float h = og * tanhf(c);
        g_hnew[b * 512 + j] = h;
        g_h1[b * 512 + j] = __float2half_rn(h);
    }
}

// ---------------------------------------------------------------------------
// HMMA approx logits: per CTA 64 vocab x 128 batch, K=512, single fp16 pass.
// 3-stage cp.async ring, ONE __syncthreads per K-chunk. Per-CTA col maxes out.
#define KC      64
#define ROWB    144                 // 64 halves (128B) + 16B pad, conflict-free
#define WTILEB  (VTILE * ROWB)      // 9216
#define HTILEB  (128 * ROWB)        // 18432
#define STAGEB  (WTILEB + HTILEB)   // 27648
#define SMEM_LOG (3 * STAGEB)       // 82944

__global__ __launch_bounds__(256, 2) void logits_mma_kernel(const float* __restrict__ bfc) {
    extern __shared__ char smem[];
    __shared__ float pv[256];
    const uint32_t sb = smem_u32(smem);
    const int tid = threadIdx.x;
    const int wid = tid >> 5;
    const int lane = tid & 31;
    const int vb = blockIdx.x * VTILE;
    const int vrow0 = (wid & 3) * 16;
    const int brow0 = (wid >> 2) * 64;

    float d0[8][4] = {};

    auto load_stage = [&](int buf, int k0) {
        const uint32_t st = sb + buf * STAGEB;
#pragma unroll
        for (int i = 0; i < 6; ++i) {
            int lin = i * 256 + tid;
            if (lin < 512) {
                int row = lin >> 3, col = lin & 7;
                cp16(st + row * ROWB + col * 16,
                     g_W1 + (size_t)(vb + row) * 512 + k0 + col * 8);
            } else {
                int idx = lin - 512;
                int row = idx >> 3, col = idx & 7;
                cp16(st + WTILEB + row * ROWB + col * 16,
                     g_h1 + (size_t)row * 512 + k0 + col * 8);
            }
        }
        CP_COMMIT();
    };

    load_stage(0, 0);
    load_stage(1, KC);

    for (int kc = 0; kc < 8; ++kc) {
        if (kc < 7) cp_wait<1>(); else cp_wait<0>();
        __syncthreads();   // stage kc visible to all; slot (kc+2)%3 free to refill
        if (kc + 2 < 8) load_stage((kc + 2) % 3, (kc + 2) * KC);
        const uint32_t st = sb + (kc % 3) * STAGEB;
#pragma unroll
        for (int ks = 0; ks < 4; ++ks) {
            const uint32_t kb = ks * 32;
            const int mat = lane >> 3;
            uint32_t a1[4];
            {
                const uint32_t row = vrow0 + (mat & 1) * 8 + (lane & 7);
                ldsm4(a1, st + row * ROWB + kb + (mat >> 1) * 16);
            }
            uint32_t b1[8][2];
#pragma unroll
            for (int j = 0; j < 4; ++j) {
                const uint32_t row = brow0 + j * 16 + (mat >> 1) * 8 + (lane & 7);
                uint32_t r[4];
                ldsm4(r, st + WTILEB + row * ROWB + kb + (mat & 1) * 16);
                b1[2 * j][0] = r[0]; b1[2 * j][1] = r[1];
                b1[2 * j + 1][0] = r[2]; b1[2 * j + 1][1] = r[3];
            }
#pragma unroll
            for (int nf = 0; nf < 8; ++nf)
                mma16816(d0[nf], a1, b1[nf]);
        }
    }

    // ---- epilogue: logits(+bias) into smem [b][64], per-column max ----
    __syncthreads();
    float* slog = (float*)smem;            // [128][68]
    const int vloc0 = vrow0 + (lane >> 2);
    const float bias0 = bfc[vb + vloc0];
    const float bias1 = bfc[vb + vloc0 + 8];
#pragma unroll
    for (int nf = 0; nf < 8; ++nf) {
        const int b0 = brow0 + nf * 8 + 2 * (lane & 3);
        slog[(b0)     * 68 + vloc0]     = d0[nf][0] + bias0;
        slog[(b0 + 1) * 68 + vloc0]     = d0[nf][1] + bias0;
        slog[(b0)     * 68 + vloc0 + 8] = d0[nf][2] + bias1;
        slog[(b0 + 1) * 68 + vloc0 + 8] = d0[nf][3] + bias1;
    }
    __syncthreads();
    {
        const int c = tid & 127;
        const int half = tid >> 7;
        const float* col = slog + c * 68 + half * 32;
        float m = col[0];
#pragma unroll 8
        for (int v = 1; v < 32; ++v) m = fmaxf(m, col[v]);
        pv[tid] = m;
    }
    __syncthreads();
    if (tid < 128)
        g_pval[(size_t)blockIdx.x * 128 + tid] = fmaxf(pv[tid], pv[tid + 128]);
}

// ---------------------------------------------------------------------------
// Fused: global max -> threshold -> exact fp32 recompute of candidate blocks
// -> exact argmax/val -> output + embedding gather + COMMIT h into g_xh.
__global__ __launch_bounds__(256) void fixup_kernel(
    const float* __restrict__ Wfc, const float* __restrict__ bfc,
    const float* __restrict__ emb, float* __restrict__ out, int step) {
    __shared__ float sh[512];
    __shared__ float sv[256];
    __shared__ int   si[256];
    __shared__ int   cand[64];
    __shared__ int   ncand;
    const int b = blockIdx.x, t = threadIdx.x;
    const int wid = t >> 5, lane = t & 31;

    for (int k = t; k < 512; k += 256) sh[k] = g_hnew[b * 512 + k];
    if (t == 0) ncand = 0;

    float m = -INFINITY;
    for (int c = t; c < NVBLK2; c += 256) m = fmaxf(m, g_pval[(size_t)c * 128 + b]);
    sv[t] = m;
    __syncthreads();
    for (int s = 128; s > 0; s >>= 1) {
        if (t < s) sv[t] = fmaxf(sv[t], sv[t + s]);
        __syncthreads();
    }
    const float gmax = sv[0];
    __syncthreads();
    const float thr = gmax - 0.01f * fmaxf(1.0f, fabsf(gmax));

    for (int c = t; c < NVBLK2; c += 256)
        if (g_pval[(size_t)c * 128 + b] >= thr) {
            int p = atomicAdd(&ncand, 1);
            if (p < 64) cand[p] = c;
        }
    __syncthreads();
    const int nc = min(ncand, 64);

    float best = -INFINITY;
    int bi = 0x7fffffff;
    for (int ci = 0; ci < nc; ++ci) {
        const int c = cand[ci];
        for (int r = wid; r < VTILE; r += 8) {
            const int v = c * VTILE + r;
            const float* w = Wfc + (size_t)v * 512;
            float acc = 0.0f;
#pragma unroll
            for (int j = 0; j < 4; ++j) {
                float4 wv = *(const float4*)(w + lane * 16 + j * 4);
                const float* hh = sh + lane * 16 + j * 4;
                acc += wv.x * hh[0] + wv.y * hh[1] + wv.z * hh[2] + wv.w * hh[3];
            }
#pragma unroll
            for (int o = 16; o; o >>= 1) acc += __shfl_xor_sync(0xffffffffu, acc, o);
            acc += bfc[v];
            if (lane == 0) {
                if (acc > best || (acc == best && v < bi)) { best = acc; bi = v; }
            }
        }
    }
    sv[t] = (lane == 0) ? best : -INFINITY;
    si[t] = (lane == 0) ? bi : 0x7fffffff;
    __syncthreads();
    for (int s = 128; s > 0; s >>= 1) {
        if (t < s) {
            float v = sv[t + s]; int ix = si[t + s];
            if (v > sv[t] || (v == sv[t] && ix < si[t])) { sv[t] = v; si[t] = ix; }
        }
        __syncthreads();
    }
    const int idx = si[0];
    if (t == 0) {
        out[b * TSTEPS + step] = (float)idx;
        out[BATCH * TSTEPS + b * TSTEPS + step] = sv[0];
    }
    for (int k = t; k < 512; k += 256) {
        g_xh[b * 1024 + k]       = emb[(size_t)idx * 512 + k];
        g_xh[b * 1024 + 512 + k] = sh[k];    // commit new h for next step's gates
    }
}

// ---------------------------------------------------------------------------
extern "C" void kernel_launch(void* const* d_in, const int* in_sizes, int n_in,
                              void* d_out, int out_size) {
    const float* features = (const float*)d_in[0];
    const float* emb = (const float*)d_in[2];
    const float* Wih = (const float*)d_in[3];
    const float* Whh = (const float*)d_in[4];
    const float* bih = (const float*)d_in[5];
    const float* bhh = (const float*)d_in[6];
    const float* Wfc = (const float*)d_in[7];
    const float* bfc = (const float*)d_in[8];
    float* out = (float*)d_out;

    cudaFuncSetAttribute(logits_mma_kernel,
                         cudaFuncAttributeMaxDynamicSharedMemorySize, SMEM_LOG);

    init_kernel<<<BATCH, 256>>>(features);
    wsplit_kernel<<<16000, 256>>>(Wfc);
    for (int t = 0; t < TSTEPS; ++t) {
        gates_pw_kernel<<<dim3(32, 4), 128>>>(Wih, Whh, bih, bhh);
        logits_mma_kernel<<<NVBLK2, 256, SMEM_LOG>>>(bfc);
        fixup_kernel<<<BATCH, 256>>>(Wfc, bfc, emb, out, t);
    }
}

// round 8
// speedup vs baseline: 1.8700x; 1.4901x over previous
#include <cuda_runtime.h>
#include <cuda_fp16.h>
#include <math.h>
#include <stdint.h>

#define BATCH   128
#define EMBED   512
#define HIDDEN  512
#define VOCAB   32000
#define TSTEPS  20
#define VTILE   64
#define NVBLK2  (VOCAB/VTILE)   // 500 logits blocks

// ---------------------------------------------------------------------------
// Persistent device scratch (re-written every launch -> deterministic)
__device__ float  g_xh[BATCH * 1024];      // [b][0:512]=x, [b][512:1024]=h (fp32)
__device__ float  g_hnew[BATCH * HIDDEN];  // freshly produced h (committed by fixup)
__device__ float  g_c[BATCH * HIDDEN];
__device__ float  g_p1v[NVBLK2 * BATCH];   // per-CTA per-column top-1 approx value
__device__ int    g_p1i[NVBLK2 * BATCH];   // per-CTA per-column top-1 vocab index
__device__ float  g_p2v[NVBLK2 * BATCH];   // per-CTA per-column top-2 approx value
__device__ __half g_W1[VOCAB * 512];       // fp16(W_fc)
__device__ __half g_h1[BATCH * 512];       // fp16(h)

__device__ __forceinline__ float sigf(float x) { return 1.0f / (1.0f + expf(-x)); }

// ---------------------------------------------------------------------------
__device__ __forceinline__ uint32_t smem_u32(const void* p) {
    uint32_t a;
    asm("{ .reg .u64 t; cvta.to.shared.u64 t, %1; cvt.u32.u64 %0, t; }" : "=r"(a) : "l"(p));
    return a;
}
__device__ __forceinline__ void cp16(uint32_t dst, const void* src) {
    asm volatile("cp.async.cg.shared.global [%0], [%1], 16;" :: "r"(dst), "l"(src) : "memory");
}
#define CP_COMMIT() asm volatile("cp.async.commit_group;" ::: "memory")
template <int N> __device__ __forceinline__ void cp_wait() {
    asm volatile("cp.async.wait_group %0;" :: "n"(N) : "memory");
}
__device__ __forceinline__ void ldsm4(uint32_t* r, uint32_t a) {
    asm volatile("ldmatrix.sync.aligned.m8n8.x4.shared.b16 {%0,%1,%2,%3}, [%4];"
                 : "=r"(r[0]), "=r"(r[1]), "=r"(r[2]), "=r"(r[3]) : "r"(a));
}
__device__ __forceinline__ void mma16816(float* d, const uint32_t* a, const uint32_t* b) {
    asm volatile(
        "mma.sync.aligned.m16n8k16.row.col.f32.f16.f16.f32 "
        "{%0,%1,%2,%3}, {%4,%5,%6,%7}, {%8,%9}, {%0,%1,%2,%3};"
        : "+f"(d[0]), "+f"(d[1]), "+f"(d[2]), "+f"(d[3])
        : "r"(a[0]), "r"(a[1]), "r"(a[2]), "r"(a[3]), "r"(b[0]), "r"(b[1]));
}

// ---------------------------------------------------------------------------
__global__ void init_kernel(const float* __restrict__ features) {
    int b = blockIdx.x, t = threadIdx.x;
    for (int k = t; k < 512; k += 256) {
        g_xh[b * 1024 + k]       = features[b * 512 + k];
        g_xh[b * 1024 + 512 + k] = 0.0f;
        g_hnew[b * 512 + k]      = 0.0f;
        g_c[b * 512 + k]         = 0.0f;
        g_h1[b * 512 + k]        = __float2half_rn(0.0f);
    }
}

// Convert W_fc -> fp16, once per launch. 4,096,000 float4s.
__global__ void wsplit_kernel(const float* __restrict__ Wfc) {
    size_t i = (size_t)blockIdx.x * blockDim.x + threadIdx.x;
    float4 v = ((const float4*)Wfc)[i];
    __half2* w1 = (__half2*)g_W1;
    w1[i * 2]     = __halves2half2(__float2half_rn(v.x), __float2half_rn(v.y));
    w1[i * 2 + 1] = __halves2half2(__float2half_rn(v.z), __float2half_rn(v.w));
}

// ---------------------------------------------------------------------------
// Fused gates + LSTM pointwise. Reads OLD h from g_xh; writes new h ONLY to
// g_hnew / g_h1 (g_xh h-half committed later by fixup -> no intra-kernel race).
__global__ __launch_bounds__(128) void gates_pw_kernel(
    const float* __restrict__ Wih, const float* __restrict__ Whh,
    const float* __restrict__ bih, const float* __restrict__ bhh) {
    __shared__ float As[16][68];
    __shared__ float Bs[16][36];
    __shared__ float sg[64][33];
    const int j0 = blockIdx.x * 16;
    const int n0 = blockIdx.y * 32;
    const int tid = threadIdx.x;
    const int lr = tid >> 2;
    const int lc = (tid & 3) * 4;
    const int tr = tid >> 3;
    const int tc = tid & 7;
    float acc[4][4] = {};

    for (int k0 = 0; k0 < 1024; k0 += 16) {
        const float* W = (k0 < 512) ? Wih : Whh;
        const int kc = (k0 < 512) ? k0 : (k0 - 512);
        const int r0 = lr,      m0 = (r0 >> 4) * 512 + j0 + (r0 & 15);
        const int r1 = lr + 32, m1 = (r1 >> 4) * 512 + j0 + (r1 & 15);
        float4 a0 = *(const float4*)(W + (size_t)m0 * 512 + kc + lc);
        float4 a1 = *(const float4*)(W + (size_t)m1 * 512 + kc + lc);
        float4 b0 = *(const float4*)(g_xh + (size_t)(n0 + lr) * 1024 + k0 + lc);
        __syncthreads();
        As[lc + 0][r0] = a0.x; As[lc + 1][r0] = a0.y;
        As[lc + 2][r0] = a0.z; As[lc + 3][r0] = a0.w;
        As[lc + 0][r1] = a1.x; As[lc + 1][r1] = a1.y;
        As[lc + 2][r1] = a1.z; As[lc + 3][r1] = a1.w;
        Bs[lc + 0][lr] = b0.x; Bs[lc + 1][lr] = b0.y;
        Bs[lc + 2][lr] = b0.z; Bs[lc + 3][lr] = b0.w;
        __syncthreads();
#pragma unroll
        for (int kk = 0; kk < 16; ++kk) {
            float av[4], bv[4];
#pragma unroll
            for (int i = 0; i < 4; ++i) av[i] = As[kk][tr * 4 + i];
#pragma unroll
            for (int j = 0; j < 4; ++j) bv[j] = Bs[kk][tc * 4 + j];
#pragma unroll
            for (int i = 0; i < 4; ++i)
#pragma unroll
                for (int j = 0; j < 4; ++j) acc[i][j] = fmaf(av[i], bv[j], acc[i][j]);
        }
    }
#pragma unroll
    for (int i = 0; i < 4; ++i) {
        const int row = tr * 4 + i;
        const int m = (row >> 4) * 512 + j0 + (row & 15);
        const float bb = bih[m] + bhh[m];
#pragma unroll
        for (int j = 0; j < 4; ++j)
            sg[row][tc * 4 + j] = acc[i][j] + bb;
    }
    __syncthreads();
#pragma unroll
    for (int q = 0; q < 4; ++q) {
        const int idx = tid * 4 + q;
        const int jl = idx >> 5;
        const int bl = idx & 31;
        const int j = j0 + jl;
        const int b = n0 + bl;
        float ig = sigf(sg[jl][bl]);
        float fg = sigf(sg[16 + jl][bl]);
        float gg = tanhf(sg[32 + jl][bl]);
        float og = sigf(sg[48 + jl][bl]);
        float c = fg * g_c[b * 512 + j] + ig * gg;
        g_c[b * 512 + j] = c;
        float h = og * tanhf(c);
        g_hnew[b * 512 + j] = h;
        g_h1[b * 512 + j] = __float2half_rn(h);
    }
}

// ---------------------------------------------------------------------------
// HMMA approx logits: per CTA 64 vocab x 128 batch, K=512, single fp16 pass.
// 3-stage cp.async ring, one __syncthreads per K-chunk.
// Epilogue: per-column TOP-2 (val1,idx1,val2) -> global arrays.
#define KC      64
#define ROWB    144                 // 64 halves (128B) + 16B pad, conflict-free
#define WTILEB  (VTILE * ROWB)      // 9216
#define HTILEB  (128 * ROWB)        // 18432
#define STAGEB  (WTILEB + HTILEB)   // 27648
#define SMEM_LOG (3 * STAGEB)       // 82944

__global__ __launch_bounds__(256, 2) void logits_mma_kernel(const float* __restrict__ bfc) {
    extern __shared__ char smem[];
    __shared__ float pv1[256];
    __shared__ int   pi1[256];
    __shared__ float pv2[256];
    const uint32_t sb = smem_u32(smem);
    const int tid = threadIdx.x;
    const int wid = tid >> 5;
    const int lane = tid & 31;
    const int vb = blockIdx.x * VTILE;
    const int vrow0 = (wid & 3) * 16;
    const int brow0 = (wid >> 2) * 64;

    float d0[8][4] = {};

    auto load_stage = [&](int buf, int k0) {
        const uint32_t st = sb + buf * STAGEB;
#pragma unroll
        for (int i = 0; i < 6; ++i) {
            int lin = i * 256 + tid;
            if (lin < 512) {
                int row = lin >> 3, col = lin & 7;
                cp16(st + row * ROWB + col * 16,
                     g_W1 + (size_t)(vb + row) * 512 + k0 + col * 8);
            } else {
                int idx = lin - 512;
                int row = idx >> 3, col = idx & 7;
                cp16(st + WTILEB + row * ROWB + col * 16,
                     g_h1 + (size_t)row * 512 + k0 + col * 8);
            }
        }
        CP_COMMIT();
    };

    load_stage(0, 0);
    load_stage(1, KC);

    for (int kc = 0; kc < 8; ++kc) {
        if (kc < 7) cp_wait<1>(); else cp_wait<0>();
        __syncthreads();
        if (kc + 2 < 8) load_stage((kc + 2) % 3, (kc + 2) * KC);
        const uint32_t st = sb + (kc % 3) * STAGEB;
#pragma unroll
        for (int ks = 0; ks < 4; ++ks) {
            const uint32_t kb = ks * 32;
            const int mat = lane >> 3;
            uint32_t a1[4];
            {
                const uint32_t row = vrow0 + (mat & 1) * 8 + (lane & 7);
                ldsm4(a1, st + row * ROWB + kb + (mat >> 1) * 16);
            }
            uint32_t b1[8][2];
#pragma unroll
            for (int j = 0; j < 4; ++j) {
                const uint32_t row = brow0 + j * 16 + (mat >> 1) * 8 + (lane & 7);
                uint32_t r[4];
                ldsm4(r, st + WTILEB + row * ROWB + kb + (mat & 1) * 16);
                b1[2 * j][0] = r[0]; b1[2 * j][1] = r[1];
                b1[2 * j + 1][0] = r[2]; b1[2 * j + 1][1] = r[3];
            }
#pragma unroll
            for (int nf = 0; nf < 8; ++nf)
                mma16816(d0[nf], a1, b1[nf]);
        }
    }

    // ---- epilogue: logits(+bias) into smem [b][64], per-column TOP-2 ----
    __syncthreads();
    float* slog = (float*)smem;            // [128][68]
    const int vloc0 = vrow0 + (lane >> 2);
    const float bias0 = bfc[vb + vloc0];
    const float bias1 = bfc[vb + vloc0 + 8];
#pragma unroll
    for (int nf = 0; nf < 8; ++nf) {
        const int b0 = brow0 + nf * 8 + 2 * (lane & 3);
        slog[(b0)     * 68 + vloc0]     = d0[nf][0] + bias0;
        slog[(b0 + 1) * 68 + vloc0]     = d0[nf][1] + bias0;
        slog[(b0)     * 68 + vloc0 + 8] = d0[nf][2] + bias1;
        slog[(b0 + 1) * 68 + vloc0 + 8] = d0[nf][3] + bias1;
    }
    __syncthreads();
    {
        // two threads per column, each scans 32 of 64 rows for top-2
        const int c = tid & 127;
        const int half = tid >> 7;
        const float* col = slog + c * 68 + half * 32;
        float v1 = col[0]; int i1 = 0;
        float v2 = -INFINITY;
#pragma unroll 8
        for (int v = 1; v < 32; ++v) {
            float x = col[v];
            if (x > v1) { v2 = v1; v1 = x; i1 = v; }
            else if (x > v2) v2 = x;
        }
        pv1[tid] = v1; pi1[tid] = half * 32 + i1; pv2[tid] = v2;
    }
    __syncthreads();
    if (tid < 128) {
        const float v1a = pv1[tid],       v2a = pv2[tid];
        const int   i1a = pi1[tid];
        const float v1b = pv1[tid + 128], v2b = pv2[tid + 128];
        const int   i1b = pi1[tid + 128];
        float t1v, t2v; int t1i;
        if (v1b > v1a) { t1v = v1b; t1i = i1b; t2v = fmaxf(v1a, v2b); }
        else           { t1v = v1a; t1i = i1a; t2v = fmaxf(v1b, v2a); }  // tie -> lower idx
        const size_t o = (size_t)blockIdx.x * 128 + tid;
        g_p1v[o] = t1v;
        g_p1i[o] = vb + t1i;
        g_p2v[o] = t2v;
    }
}

// ---------------------------------------------------------------------------
// Fixup: gmax over block top-1s -> threshold -> exact fp32 dots for candidate
// ROWS (block top-1s above thr); full 64-row rescan only when a block's top-2
// also clears thr (rare). Then output + embedding gather + commit h.
__global__ __launch_bounds__(256) void fixup_kernel(
    const float* __restrict__ Wfc, const float* __restrict__ bfc,
    const float* __restrict__ emb, float* __restrict__ out, int step) {
    __shared__ float sh[512];
    __shared__ float sv[256];
    __shared__ int   si[256];
    __shared__ int   rows[128];
    __shared__ int   blks[16];
    __shared__ int   nrow, nblk;
    const int b = blockIdx.x, t = threadIdx.x;
    const int wid = t >> 5, lane = t & 31;

    for (int k = t; k < 512; k += 256) sh[k] = g_hnew[b * 512 + k];
    if (t == 0) { nrow = 0; nblk = 0; }

    float m = -INFINITY;
    for (int c = t; c < NVBLK2; c += 256) m = fmaxf(m, g_p1v[(size_t)c * 128 + b]);
    sv[t] = m;
    __syncthreads();
    for (int s = 128; s > 0; s >>= 1) {
        if (t < s) sv[t] = fmaxf(sv[t], sv[t + s]);
        __syncthreads();
    }
    const float gmax = sv[0];
    __syncthreads();
    const float thr = gmax - 0.01f * fmaxf(1.0f, fabsf(gmax));

    for (int c = t; c < NVBLK2; c += 256) {
        const size_t o = (size_t)c * 128 + b;
        if (g_p1v[o] >= thr) {
            int p = atomicAdd(&nrow, 1);
            if (p < 128) rows[p] = g_p1i[o];
        }
        if (g_p2v[o] >= thr) {
            int q = atomicAdd(&nblk, 1);
            if (q < 16) blks[q] = c;
        }
    }
    __syncthreads();
    const int nr = min(nrow, 128);
    const int nb = min(nblk, 16);

    float best = -INFINITY;
    int bi = 0x7fffffff;
    // exact dots for candidate rows (warp per row)
    for (int ri = wid; ri < nr; ri += 8) {
        const int v = rows[ri];
        const float* w = Wfc + (size_t)v * 512;
        float acc = 0.0f;
#pragma unroll
        for (int j = 0; j < 4; ++j) {
            float4 wv = *(const float4*)(w + lane * 16 + j * 4);
            const float* hh = sh + lane * 16 + j * 4;
            acc += wv.x * hh[0] + wv.y * hh[1] + wv.z * hh[2] + wv.w * hh[3];
        }
#pragma unroll
        for (int o = 16; o; o >>= 1) acc += __shfl_xor_sync(0xffffffffu, acc, o);
        acc += bfc[v];
        if (lane == 0) {
            if (acc > best || (acc == best && v < bi)) { best = acc; bi = v; }
        }
    }
    // rare: full block rescan when top-2 cleared the threshold
    for (int ci = 0; ci < nb; ++ci) {
        const int c = blks[ci];
        for (int r = wid; r < VTILE; r += 8) {
            const int v = c * VTILE + r;
            const float* w = Wfc + (size_t)v * 512;
            float acc = 0.0f;
#pragma unroll
            for (int j = 0; j < 4; ++j) {
                float4 wv = *(const float4*)(w + lane * 16 + j * 4);
                const float* hh = sh + lane * 16 + j * 4;
                acc += wv.x * hh[0] + wv.y * hh[1] + wv.z * hh[2] + wv.w * hh[3];
            }
#pragma unroll
            for (int o = 16; o; o >>= 1) acc += __shfl_xor_sync(0xffffffffu, acc, o);
            acc += bfc[v];
            if (lane == 0) {
                if (acc > best || (acc == best && v < bi)) { best = acc; bi = v; }
            }
        }
    }
    sv[t] = (lane == 0) ? best : -INFINITY;
    si[t] = (lane == 0) ? bi : 0x7fffffff;
    __syncthreads();
    for (int s = 128; s > 0; s >>= 1) {
        if (t < s) {
            float v = sv[t + s]; int ix = si[t + s];
            if (v > sv[t] || (v == sv[t] && ix < si[t])) { sv[t] = v; si[t] = ix; }
        }
        __syncthreads();
    }
    const int idx = si[0];
    if (t == 0) {
        out[b * TSTEPS + step] = (float)idx;
        out[BATCH * TSTEPS + b * TSTEPS + step] = sv[0];
    }
    for (int k = t; k < 512; k += 256) {
        g_xh[b * 1024 + k]       = emb[(size_t)idx * 512 + k];
        g_xh[b * 1024 + 512 + k] = sh[k];    // commit new h for next step's gates
    }
}

// ---------------------------------------------------------------------------
extern "C" void kernel_launch(void* const* d_in, const int* in_sizes, int n_in,
                              void* d_out, int out_size) {
    const float* features = (const float*)d_in[0];
    const float* emb = (const float*)d_in[2];
    const float* Wih = (const float*)d_in[3];
    const float* Whh = (const float*)d_in[4];
    const float* bih = (const float*)d_in[5];
    const float* bhh = (const float*)d_in[6];
    const float* Wfc = (const float*)d_in[7];
    const float* bfc = (const float*)d_in[8];
    float* out = (float*)d_out;

    cudaFuncSetAttribute(logits_mma_kernel,
                         cudaFuncAttributeMaxDynamicSharedMemorySize, SMEM_LOG);

    init_kernel<<<BATCH, 256>>>(features);
    wsplit_kernel<<<16000, 256>>>(Wfc);
    for (int t = 0; t < TSTEPS; ++t) {
        gates_pw_kernel<<<dim3(32, 4), 128>>>(Wih, Whh, bih, bhh);
        logits_mma_kernel<<<NVBLK2, 256, SMEM_LOG>>>(bfc);
        fixup_kernel<<<BATCH, 256>>>(Wfc, bfc, emb, out, t);
    }
}

// round 9
// speedup vs baseline: 3.0964x; 1.6558x over previous
#include <cuda_runtime.h>
#include <cuda_fp16.h>
#include <math.h>
#include <stdint.h>

#define BATCH   128
#define EMBED   512
#define HIDDEN  512
#define VOCAB   32000
#define TSTEPS  20
#define VTILE   64
#define NVBLK2  (VOCAB/VTILE)   // 500 logits blocks

// ---------------------------------------------------------------------------
// Persistent device scratch (re-written every launch -> deterministic)
__device__ float  g_hnew[BATCH * HIDDEN];  // fresh h fp32 (for fixup exact dots)
__device__ float  g_c[BATCH * HIDDEN];
__device__ float  g_p1v[NVBLK2 * BATCH];
__device__ int    g_p1i[NVBLK2 * BATCH];
__device__ float  g_p2v[NVBLK2 * BATCH];
__device__ __half g_W1[VOCAB * 512];        // fp16(W_fc)   (logits)
__device__ __half g_hn1[BATCH * 512];       // fp16(h) for logits
__device__ __half g_W1c[2048 * 1024];       // hi split of Wcat=[Wih|Whh]
__device__ __half g_W2c[2048 * 1024];       // (Wcat - W1c)*1024
__device__ __half g_xh1[BATCH * 1024];      // hi split of [x|h] (committed)
__device__ __half g_xh2[BATCH * 1024];      // residual*1024
__device__ float  g_bias[2048];             // bih + bhh

__device__ __forceinline__ float sigf(float x) { return 1.0f / (1.0f + expf(-x)); }

// ---------------------------------------------------------------------------
__device__ __forceinline__ uint32_t smem_u32(const void* p) {
    uint32_t a;
    asm("{ .reg .u64 t; cvta.to.shared.u64 t, %1; cvt.u32.u64 %0, t; }" : "=r"(a) : "l"(p));
    return a;
}
__device__ __forceinline__ void cp16(uint32_t dst, const void* src) {
    asm volatile("cp.async.cg.shared.global [%0], [%1], 16;" :: "r"(dst), "l"(src) : "memory");
}
#define CP_COMMIT() asm volatile("cp.async.commit_group;" ::: "memory")
template <int N> __device__ __forceinline__ void cp_wait() {
    asm volatile("cp.async.wait_group %0;" :: "n"(N) : "memory");
}
__device__ __forceinline__ void ldsm4(uint32_t* r, uint32_t a) {
    asm volatile("ldmatrix.sync.aligned.m8n8.x4.shared.b16 {%0,%1,%2,%3}, [%4];"
                 : "=r"(r[0]), "=r"(r[1]), "=r"(r[2]), "=r"(r[3]) : "r"(a));
}
__device__ __forceinline__ void mma16816(float* d, const uint32_t* a, const uint32_t* b) {
    asm volatile(
        "mma.sync.aligned.m16n8k16.row.col.f32.f16.f16.f32 "
        "{%0,%1,%2,%3}, {%4,%5,%6,%7}, {%8,%9}, {%0,%1,%2,%3};"
        : "+f"(d[0]), "+f"(d[1]), "+f"(d[2]), "+f"(d[3])
        : "r"(a[0]), "r"(a[1]), "r"(a[2]), "r"(a[3]), "r"(b[0]), "r"(b[1]));
}

// ---------------------------------------------------------------------------
__global__ void init_kernel(const float* __restrict__ features) {
    int b = blockIdx.x, t = threadIdx.x;
    for (int k = t; k < 512; k += 256) {
        float x = features[b * 512 + k];
        __half x1 = __float2half_rn(x);
        g_xh1[b * 1024 + k] = x1;
        g_xh2[b * 1024 + k] = __float2half_rn((x - __half2float(x1)) * 1024.0f);
        g_xh1[b * 1024 + 512 + k] = __float2half_rn(0.0f);
        g_xh2[b * 1024 + 512 + k] = __float2half_rn(0.0f);
        g_c[b * 512 + k]    = 0.0f;
        g_hnew[b * 512 + k] = 0.0f;
        g_hn1[b * 512 + k]  = __float2half_rn(0.0f);
    }
}

// fp16 cast of W_fc (logits), once per launch.
__global__ void wsplit_kernel(const float* __restrict__ Wfc) {
    size_t i = (size_t)blockIdx.x * blockDim.x + threadIdx.x;
    float4 v = ((const float4*)Wfc)[i];
    __half2* w1 = (__half2*)g_W1;
    w1[i * 2]     = __halves2half2(__float2half_rn(v.x), __float2half_rn(v.y));
    w1[i * 2 + 1] = __halves2half2(__float2half_rn(v.z), __float2half_rn(v.w));
}

// 2-term split of Wcat = [Wih | Whh] (2048 x 1024) + bias precompute.
__global__ void wsplit2_kernel(const float* __restrict__ Wih,
                               const float* __restrict__ Whh,
                               const float* __restrict__ bih,
                               const float* __restrict__ bhh) {
    size_t i = (size_t)blockIdx.x * blockDim.x + threadIdx.x;  // float4 idx, 524288
    int m  = (int)(i >> 8);
    int kq = ((int)i & 255) * 4;
    float4 v = (kq < 512) ? *(const float4*)(Wih + (size_t)m * 512 + kq)
                          : *(const float4*)(Whh + (size_t)m * 512 + kq - 512);
    __half a0 = __float2half_rn(v.x), a1 = __float2half_rn(v.y);
    __half a2 = __float2half_rn(v.z), a3 = __float2half_rn(v.w);
    __half2* w1 = (__half2*)(g_W1c + (size_t)m * 1024 + kq);
    __half2* w2 = (__half2*)(g_W2c + (size_t)m * 1024 + kq);
    w1[0] = __halves2half2(a0, a1);
    w1[1] = __halves2half2(a2, a3);
    w2[0] = __halves2half2(__float2half_rn((v.x - __half2float(a0)) * 1024.0f),
                           __float2half_rn((v.y - __half2float(a1)) * 1024.0f));
    w2[1] = __halves2half2(__float2half_rn((v.z - __half2float(a2)) * 1024.0f),
                           __float2half_rn((v.w - __half2float(a3)) * 1024.0f));
    if (kq == 0) g_bias[m] = bih[m] + bhh[m];
}

// ---------------------------------------------------------------------------
// HMMA gates (2-term split) + fused LSTM pointwise.
// CTA: 64 gate-rows (16 j x 4 gates, m=(r>>4)*512+j0+(r&15)) x 32 batch, K=1024.
// d0=W1*x1, d1=W1*x2+W2*x1; gate = d0 + d1/1024 + bias.
#define GKC     64
#define GROWB   144
#define GW_T    (64 * GROWB)                 // 9216  (one W tile)
#define GB_T    (32 * GROWB)                 // 4608  (one B tile)
#define GSTAGE  (2 * GW_T + 2 * GB_T)        // 27648
#define SMEM_G  (3 * GSTAGE)                 // 82944

__global__ __launch_bounds__(256, 2) void gates_mma_kernel() {
    extern __shared__ char smem[];
    const uint32_t sb = smem_u32(smem);
    const int tid = threadIdx.x;
    const int wid = tid >> 5;
    const int lane = tid & 31;
    const int j0 = blockIdx.x * 16;
    const int n0 = blockIdx.y * 32;
    const int vrow0 = (wid & 3) * 16;   // M (gate-row) offset
    const int bcol0 = (wid >> 2) * 16;  // N (batch) offset

    float d0[2][4] = {};
    float d1[2][4] = {};

    // 1536 granules of 16B per stage: W1 512, W2 512, B1 256, B2 256
    auto load_stage = [&](int buf, int k0) {
        const uint32_t st = sb + buf * GSTAGE;
#pragma unroll
        for (int i = 0; i < 6; ++i) {
            int lin = i * 256 + tid;
            if (lin < 1024) {
                int half2nd = lin >= 512;
                int idx = lin & 511;
                int r = idx >> 3, c = idx & 7;
                int m = (r >> 4) * 512 + j0 + (r & 15);
                const __half* src = (half2nd ? g_W2c : g_W1c) + (size_t)m * 1024 + k0 + c * 8;
                cp16(st + half2nd * GW_T + r * GROWB + c * 16, src);
            } else {
                int half2nd = lin >= 1280;
                int idx = (lin - 1024) & 255;
                int r = idx >> 3, c = idx & 7;
                const __half* src = (half2nd ? g_xh2 : g_xh1) + (size_t)(n0 + r) * 1024 + k0 + c * 8;
                cp16(st + 2 * GW_T + half2nd * GB_T + r * GROWB + c * 16, src);
            }
        }
        CP_COMMIT();
    };

    load_stage(0, 0);
    load_stage(1, GKC);

    for (int kc = 0; kc < 16; ++kc) {
        if (kc < 15) cp_wait<1>(); else cp_wait<0>();
        __syncthreads();
        if (kc + 2 < 16) load_stage((kc + 2) % 3, (kc + 2) * GKC);
        const uint32_t st = sb + (kc % 3) * GSTAGE;
#pragma unroll
        for (int ks = 0; ks < 4; ++ks) {
            const uint32_t kb = ks * 32;
            const int mat = lane >> 3;
            uint32_t a1[4], a2[4];
            {
                const uint32_t row = vrow0 + (mat & 1) * 8 + (lane & 7);
                const uint32_t ao = row * GROWB + kb + (mat >> 1) * 16;
                ldsm4(a1, st + ao);
                ldsm4(a2, st + GW_T + ao);
            }
            uint32_t b1[2][2], b2[2][2];
            {
                const uint32_t row = bcol0 + (mat >> 1) * 8 + (lane & 7);
                const uint32_t bo = row * GROWB + kb + (mat & 1) * 16;
                uint32_t r[4];
                ldsm4(r, st + 2 * GW_T + bo);
                b1[0][0] = r[0]; b1[0][1] = r[1]; b1[1][0] = r[2]; b1[1][1] = r[3];
                ldsm4(r, st + 2 * GW_T + GB_T + bo);
                b2[0][0] = r[0]; b2[0][1] = r[1]; b2[1][0] = r[2]; b2[1][1] = r[3];
            }
#pragma unroll
            for (int nf = 0; nf < 2; ++nf) {
                mma16816(d0[nf], a1, b1[nf]);
                mma16816(d1[nf], a1, b2[nf]);
                mma16816(d1[nf], a2, b1[nf]);
            }
        }
    }

    // ---- epilogue: combine into sg[64][33], then pointwise ----
    __syncthreads();
    float* sg = (float*)smem;   // [64][33]
    const int r0 = vrow0 + (lane >> 2);
    const int r1 = r0 + 8;
#pragma unroll
    for (int nf = 0; nf < 2; ++nf) {
        const int c = bcol0 + nf * 8 + 2 * (lane & 3);
        sg[r0 * 33 + c]     = d0[nf][0] + d1[nf][0] * 0.0009765625f;
        sg[r0 * 33 + c + 1] = d0[nf][1] + d1[nf][1] * 0.0009765625f;
        sg[r1 * 33 + c]     = d0[nf][2] + d1[nf][2] * 0.0009765625f;
        sg[r1 * 33 + c + 1] = d0[nf][3] + d1[nf][3] * 0.0009765625f;
    }
    __syncthreads();
#pragma unroll
    for (int q = 0; q < 2; ++q) {
        const int idx = tid * 2 + q;       // 0..511
        const int jl = idx >> 5;
        const int bl = idx & 31;
        const int j = j0 + jl;
        const int b = n0 + bl;
        float ig = sigf(sg[(jl)      * 33 + bl] + g_bias[j]);
        float fg = sigf(sg[(16 + jl) * 33 + bl] + g_bias[512 + j]);
        float gg = tanhf(sg[(32 + jl) * 33 + bl] + g_bias[1024 + j]);
        float og = sigf(sg[(48 + jl) * 33 + bl] + g_bias[1536 + j]);
        float c = fg * g_c[b * 512 + j] + ig * gg;
        g_c[b * 512 + j] = c;
        float h = og * tanhf(c);
        g_hnew[b * 512 + j] = h;
        g_hn1[b * 512 + j] = __float2half_rn(h);
    }
}

// ---------------------------------------------------------------------------
// HMMA approx logits (unchanged from R8, reads g_hn1): per CTA 64v x 128b,
// K=512, 3-stage ring; epilogue per-column TOP-2.
#define KC      64
#define ROWB    144
#define WTILEB  (VTILE * ROWB)
#define HTILEB  (128 * ROWB)
#define STAGEB  (WTILEB + HTILEB)
#define SMEM_LOG (3 * STAGEB)

__global__ __launch_bounds__(256, 2) void logits_mma_kernel(const float* __restrict__ bfc) {
    extern __shared__ char smem[];
    __shared__ float pv1[256];
    __shared__ int   pi1[256];
    __shared__ float pv2[256];
    const uint32_t sb = smem_u32(smem);
    const int tid = threadIdx.x;
    const int wid = tid >> 5;
    const int lane = tid & 31;
    const int vb = blockIdx.x * VTILE;
    const int vrow0 = (wid & 3) * 16;
    const int brow0 = (wid >> 2) * 64;

    float d0[8][4] = {};

    auto load_stage = [&](int buf, int k0) {
        const uint32_t st = sb + buf * STAGEB;
#pragma unroll
        for (int i = 0; i < 6; ++i) {
            int lin = i * 256 + tid;
            if (lin < 512) {
                int row = lin >> 3, col = lin & 7;
                cp16(st + row * ROWB + col * 16,
                     g_W1 + (size_t)(vb + row) * 512 + k0 + col * 8);
            } else {
                int idx = lin - 512;
                int row = idx >> 3, col = idx & 7;
                cp16(st + WTILEB + row * ROWB + col * 16,
                     g_hn1 + (size_t)row * 512 + k0 + col * 8);
            }
        }
        CP_COMMIT();
    };

    load_stage(0, 0);
    load_stage(1, KC);

    for (int kc = 0; kc < 8; ++kc) {
        if (kc < 7) cp_wait<1>(); else cp_wait<0>();
        __syncthreads();
        if (kc + 2 < 8) load_stage((kc + 2) % 3, (kc + 2) * KC);
        const uint32_t st = sb + (kc % 3) * STAGEB;
#pragma unroll
        for (int ks = 0; ks < 4; ++ks) {
            const uint32_t kb = ks * 32;
            const int mat = lane >> 3;
            uint32_t a1[4];
            {
                const uint32_t row = vrow0 + (mat & 1) * 8 + (lane & 7);
                ldsm4(a1, st + row * ROWB + kb + (mat >> 1) * 16);
            }
            uint32_t b1[8][2];
#pragma unroll
            for (int j = 0; j < 4; ++j) {
                const uint32_t row = brow0 + j * 16 + (mat >> 1) * 8 + (lane & 7);
                uint32_t r[4];
                ldsm4(r, st + WTILEB + row * ROWB + kb + (mat & 1) * 16);
                b1[2 * j][0] = r[0]; b1[2 * j][1] = r[1];
                b1[2 * j + 1][0] = r[2]; b1[2 * j + 1][1] = r[3];
            }
#pragma unroll
            for (int nf = 0; nf < 8; ++nf)
                mma16816(d0[nf], a1, b1[nf]);
        }
    }

    __syncthreads();
    float* slog = (float*)smem;            // [128][68]
    const int vloc0 = vrow0 + (lane >> 2);
    const float bias0 = bfc[vb + vloc0];
    const float bias1 = bfc[vb + vloc0 + 8];
#pragma unroll
    for (int nf = 0; nf < 8; ++nf) {
        const int b0 = brow0 + nf * 8 + 2 * (lane & 3);
        slog[(b0)     * 68 + vloc0]     = d0[nf][0] + bias0;
        slog[(b0 + 1) * 68 + vloc0]     = d0[nf][1] + bias0;
        slog[(b0)     * 68 + vloc0 + 8] = d0[nf][2] + bias1;
        slog[(b0 + 1) * 68 + vloc0 + 8] = d0[nf][3] + bias1;
    }
    __syncthreads();
    {
        const int c = tid & 127;
        const int half = tid >> 7;
        const float* col = slog + c * 68 + half * 32;
        float v1 = col[0]; int i1 = 0;
        float v2 = -INFINITY;
#pragma unroll 8
        for (int v = 1; v < 32; ++v) {
            float x = col[v];
            if (x > v1) { v2 = v1; v1 = x; i1 = v; }
            else if (x > v2) v2 = x;
        }
        pv1[tid] = v1; pi1[tid] = half * 32 + i1; pv2[tid] = v2;
    }
    __syncthreads();
    if (tid < 128) {
        const float v1a = pv1[tid],       v2a = pv2[tid];
        const int   i1a = pi1[tid];
        const float v1b = pv1[tid + 128], v2b = pv2[tid + 128];
        const int   i1b = pi1[tid + 128];
        float t1v, t2v; int t1i;
        if (v1b > v1a) { t1v = v1b; t1i = i1b; t2v = fmaxf(v1a, v2b); }
        else           { t1v = v1a; t1i = i1a; t2v = fmaxf(v1b, v2a); }
        const size_t o = (size_t)blockIdx.x * 128 + tid;
        g_p1v[o] = t1v;
        g_p1i[o] = vb + t1i;
        g_p2v[o] = t2v;
    }
}

// ---------------------------------------------------------------------------
// Fixup (as R8) + commit of x/h fp16 SPLITS for next step's gates.
__global__ __launch_bounds__(256) void fixup_kernel(
    const float* __restrict__ Wfc, const float* __restrict__ bfc,
    const float* __restrict__ emb, float* __restrict__ out, int step) {
    __shared__ float sh[512];
    __shared__ float sv[256];
    __shared__ int   si[256];
    __shared__ int   rows[128];
    __shared__ int   blks[16];
    __shared__ int   nrow, nblk;
    const int b = blockIdx.x, t = threadIdx.x;
    const int wid = t >> 5, lane = t & 31;

    for (int k = t; k < 512; k += 256) sh[k] = g_hnew[b * 512 + k];
    if (t == 0) { nrow = 0; nblk = 0; }

    float m = -INFINITY;
    for (int c = t; c < NVBLK2; c += 256) m = fmaxf(m, g_p1v[(size_t)c * 128 + b]);
    sv[t] = m;
    __syncthreads();
    for (int s = 128; s > 0; s >>= 1) {
        if (t < s) sv[t] = fmaxf(sv[t], sv[t + s]);
        __syncthreads();
    }
    const float gmax = sv[0];
    __syncthreads();
    const float thr = gmax - 0.01f * fmaxf(1.0f, fabsf(gmax));

    for (int c = t; c < NVBLK2; c += 256) {
        const size_t o = (size_t)c * 128 + b;
        if (g_p1v[o] >= thr) {
            int p = atomicAdd(&nrow, 1);
            if (p < 128) rows[p] = g_p1i[o];
        }
        if (g_p2v[o] >= thr) {
            int q = atomicAdd(&nblk, 1);
            if (q < 16) blks[q] = c;
        }
    }
    __syncthreads();
    const int nr = min(nrow, 128);
    const int nb = min(nblk, 16);

    float best = -INFINITY;
    int bi = 0x7fffffff;
    for (int ri = wid; ri < nr; ri += 8) {
        const int v = rows[ri];
        const float* w = Wfc + (size_t)v * 512;
        float acc = 0.0f;
#pragma unroll
        for (int j = 0; j < 4; ++j) {
            float4 wv = *(const float4*)(w + lane * 16 + j * 4);
            const float* hh = sh + lane * 16 + j * 4;
            acc += wv.x * hh[0] + wv.y * hh[1] + wv.z * hh[2] + wv.w * hh[3];
        }
#pragma unroll
        for (int o = 16; o; o >>= 1) acc += __shfl_xor_sync(0xffffffffu, acc, o);
        acc += bfc[v];
        if (lane == 0) {
            if (acc > best || (acc == best && v < bi)) { best = acc; bi = v; }
        }
    }
    for (int ci = 0; ci < nb; ++ci) {
        const int c = blks[ci];
        for (int r = wid; r < VTILE; r += 8) {
            const int v = c * VTILE + r;
            const float* w = Wfc + (size_t)v * 512;
            float acc = 0.0f;
#pragma unroll
            for (int j = 0; j < 4; ++j) {
                float4 wv = *(const float4*)(w + lane * 16 + j * 4);
                const float* hh = sh + lane * 16 + j * 4;
                acc += wv.x * hh[0] + wv.y * hh[1] + wv.z * hh[2] + wv.w * hh[3];
            }
#pragma unroll
            for (int o = 16; o; o >>= 1) acc += __shfl_xor_sync(0xffffffffu, acc, o);
            acc += bfc[v];
            if (lane == 0) {
                if (acc > best || (acc == best && v < bi)) { best = acc; bi = v; }
            }
        }
    }
    sv[t] = (lane == 0) ? best : -INFINITY;
    si[t] = (lane == 0) ? bi : 0x7fffffff;
    __syncthreads();
    for (int s = 128; s > 0; s >>= 1) {
        if (t < s) {
            float v = sv[t + s]; int ix = si[t + s];
            if (v > sv[t] || (v == sv[t] && ix < si[t])) { sv[t] = v; si[t] = ix; }
        }
        __syncthreads();
    }
    const int idx = si[0];
    if (t == 0) {
        out[b * TSTEPS + step] = (float)idx;
        out[BATCH * TSTEPS + b * TSTEPS + step] = sv[0];
    }
    for (int k = t; k < 512; k += 256) {
        float x = emb[(size_t)idx * 512 + k];
        __half x1 = __float2half_rn(x);
        g_xh1[b * 1024 + k] = x1;
        g_xh2[b * 1024 + k] = __float2half_rn((x - __half2float(x1)) * 1024.0f);
        float h = sh[k];
        __half h1 = __float2half_rn(h);
        g_xh1[b * 1024 + 512 + k] = h1;
        g_xh2[b * 1024 + 512 + k] = __float2half_rn((h - __half2float(h1)) * 1024.0f);
    }
}

// ---------------------------------------------------------------------------
extern "C" void kernel_launch(void* const* d_in, const int* in_sizes, int n_in,
                              void* d_out, int out_size) {
    const float* features = (const float*)d_in[0];
    const float* emb = (const float*)d_in[2];
    const float* Wih = (const float*)d_in[3];
    const float* Whh = (const float*)d_in[4];
    const float* bih = (const float*)d_in[5];
    const float* bhh = (const float*)d_in[6];
    const float* Wfc = (const float*)d_in[7];
    const float* bfc = (const float*)d_in[8];
    float* out = (float*)d_out;

    cudaFuncSetAttribute(logits_mma_kernel,
                         cudaFuncAttributeMaxDynamicSharedMemorySize, SMEM_LOG);
    cudaFuncSetAttribute(gates_mma_kernel,
                         cudaFuncAttributeMaxDynamicSharedMemorySize, SMEM_G);

    init_kernel<<<BATCH, 256>>>(features);
    wsplit_kernel<<<16000, 256>>>(Wfc);
    wsplit2_kernel<<<2048, 256>>>(Wih, Whh, bih, bhh);
    for (int t = 0; t < TSTEPS; ++t) {
        gates_mma_kernel<<<dim3(32, 4), 256, SMEM_G>>>();
        logits_mma_kernel<<<NVBLK2, 256, SMEM_LOG>>>(bfc);
        fixup_kernel<<<BATCH, 256>>>(Wfc, bfc, emb, out, t);
    }
}

// round 10
// speedup vs baseline: 3.1759x; 1.0257x over previous
#include <cuda_runtime.h>
#include <cuda_fp16.h>
#include <math.h>
#include <stdint.h>

#define BATCH   128
#define EMBED   512
#define HIDDEN  512
#define VOCAB   32000
#define TSTEPS  20
#define VTILE   64
#define NVBLK2  (VOCAB/VTILE)   // 500 logits blocks

// ---------------------------------------------------------------------------
// Persistent device scratch (re-written every launch -> deterministic)
__device__ float  g_hnew[BATCH * HIDDEN];
__device__ float  g_c[BATCH * HIDDEN];
__device__ float  g_p1v[NVBLK2 * BATCH];
__device__ int    g_p1i[NVBLK2 * BATCH];
__device__ float  g_p2v[NVBLK2 * BATCH];
__device__ __half g_W1[VOCAB * 512];        // fp16(W_fc)
__device__ __half g_hn1[BATCH * 512];       // fp16(h) for logits
__device__ __half g_W1c[2048 * 1024];       // hi split of Wcat=[Wih|Whh]
__device__ __half g_W2c[2048 * 1024];       // (Wcat - W1c)*1024
__device__ __half g_xh1[BATCH * 1024];      // hi split of [x|h]
__device__ __half g_xh2[BATCH * 1024];      // residual*1024
__device__ float  g_bias[2048];

__device__ __forceinline__ float sigf(float x) { return 1.0f / (1.0f + expf(-x)); }

// ---------------------------------------------------------------------------
__device__ __forceinline__ uint32_t smem_u32(const void* p) {
    uint32_t a;
    asm("{ .reg .u64 t; cvta.to.shared.u64 t, %1; cvt.u32.u64 %0, t; }" : "=r"(a) : "l"(p));
    return a;
}
__device__ __forceinline__ void cp16(uint32_t dst, const void* src) {
    asm volatile("cp.async.cg.shared.global [%0], [%1], 16;" :: "r"(dst), "l"(src) : "memory");
}
#define CP_COMMIT() asm volatile("cp.async.commit_group;" ::: "memory")
template <int N> __device__ __forceinline__ void cp_wait() {
    asm volatile("cp.async.wait_group %0;" :: "n"(N) : "memory");
}
__device__ __forceinline__ void ldsm4(uint32_t* r, uint32_t a) {
    asm volatile("ldmatrix.sync.aligned.m8n8.x4.shared.b16 {%0,%1,%2,%3}, [%4];"
                 : "=r"(r[0]), "=r"(r[1]), "=r"(r[2]), "=r"(r[3]) : "r"(a));
}
__device__ __forceinline__ void mma16816(float* d, const uint32_t* a, const uint32_t* b) {
    asm volatile(
        "mma.sync.aligned.m16n8k16.row.col.f32.f16.f16.f32 "
        "{%0,%1,%2,%3}, {%4,%5,%6,%7}, {%8,%9}, {%0,%1,%2,%3};"
        : "+f"(d[0]), "+f"(d[1]), "+f"(d[2]), "+f"(d[3])
        : "r"(a[0]), "r"(a[1]), "r"(a[2]), "r"(a[3]), "r"(b[0]), "r"(b[1]));
}

// ---------------------------------------------------------------------------
__global__ void init_kernel(const float* __restrict__ features) {
    int b = blockIdx.x, t = threadIdx.x;
    for (int k = t; k < 512; k += 256) {
        float x = features[b * 512 + k];
        __half x1 = __float2half_rn(x);
        g_xh1[b * 1024 + k] = x1;
        g_xh2[b * 1024 + k] = __float2half_rn((x - __half2float(x1)) * 1024.0f);
        g_xh1[b * 1024 + 512 + k] = __float2half_rn(0.0f);
        g_xh2[b * 1024 + 512 + k] = __float2half_rn(0.0f);
        g_c[b * 512 + k]    = 0.0f;
        g_hnew[b * 512 + k] = 0.0f;
        g_hn1[b * 512 + k]  = __float2half_rn(0.0f);
    }
}

__global__ void wsplit_kernel(const float* __restrict__ Wfc) {
    size_t i = (size_t)blockIdx.x * blockDim.x + threadIdx.x;
    float4 v = ((const float4*)Wfc)[i];
    __half2* w1 = (__half2*)g_W1;
    w1[i * 2]     = __halves2half2(__float2half_rn(v.x), __float2half_rn(v.y));
    w1[i * 2 + 1] = __halves2half2(__float2half_rn(v.z), __float2half_rn(v.w));
}

__global__ void wsplit2_kernel(const float* __restrict__ Wih,
                               const float* __restrict__ Whh,
                               const float* __restrict__ bih,
                               const float* __restrict__ bhh) {
    size_t i = (size_t)blockIdx.x * blockDim.x + threadIdx.x;
    int m  = (int)(i >> 8);
    int kq = ((int)i & 255) * 4;
    float4 v = (kq < 512) ? *(const float4*)(Wih + (size_t)m * 512 + kq)
                          : *(const float4*)(Whh + (size_t)m * 512 + kq - 512);
    __half a0 = __float2half_rn(v.x), a1 = __float2half_rn(v.y);
    __half a2 = __float2half_rn(v.z), a3 = __float2half_rn(v.w);
    __half2* w1 = (__half2*)(g_W1c + (size_t)m * 1024 + kq);
    __half2* w2 = (__half2*)(g_W2c + (size_t)m * 1024 + kq);
    w1[0] = __halves2half2(a0, a1);
    w1[1] = __halves2half2(a2, a3);
    w2[0] = __halves2half2(__float2half_rn((v.x - __half2float(a0)) * 1024.0f),
                           __float2half_rn((v.y - __half2float(a1)) * 1024.0f));
    w2[1] = __halves2half2(__float2half_rn((v.z - __half2float(a2)) * 1024.0f),
                           __float2half_rn((v.w - __half2float(a3)) * 1024.0f));
    if (kq == 0) g_bias[m] = bih[m] + bhh[m];
}

// ---------------------------------------------------------------------------
// HMMA gates (2-term split) + fused pointwise. Tile 32 gate-rows x 32 batch,
// 256 CTAs x 128 threads (4 warps, warp tile 16x16). 3-stage ring, K=1024.
// Row r (0..31) -> m = (r>>3)*512 + j0 + (r&7);  j0 = blockIdx.x*8.
#define GKC     64
#define GROWB   144
#define GW_T    (32 * GROWB)                 // 4608
#define GB_T    (32 * GROWB)                 // 4608
#define GSTAGE  (2 * GW_T + 2 * GB_T)        // 18432
#define SMEM_G  (3 * GSTAGE)                 // 55296

__global__ __launch_bounds__(128, 2) void gates_mma_kernel() {
    extern __shared__ char smem[];
    const uint32_t sb = smem_u32(smem);
    const int tid = threadIdx.x;
    const int wid = tid >> 5;
    const int lane = tid & 31;
    const int j0 = blockIdx.x * 8;
    const int n0 = blockIdx.y * 32;
    const int vrow0 = (wid & 1) * 16;
    const int bcol0 = (wid >> 1) * 16;

    float d0[2][4] = {};
    float d1[2][4] = {};

    // 1024 granules/stage: W1 256, W2 256, B1 256, B2 256 ; 8 per thread
    auto load_stage = [&](int buf, int k0) {
        const uint32_t st = sb + buf * GSTAGE;
#pragma unroll
        for (int i = 0; i < 8; ++i) {
            int lin = i * 128 + tid;
            if (lin < 512) {
                int half2nd = lin >= 256;
                int idx = lin & 255;
                int r = idx >> 3, c = idx & 7;
                int m = (r >> 3) * 512 + j0 + (r & 7);
                const __half* src = (half2nd ? g_W2c : g_W1c) + (size_t)m * 1024 + k0 + c * 8;
                cp16(st + half2nd * GW_T + r * GROWB + c * 16, src);
            } else {
                int rel = lin - 512;
                int half2nd = rel >= 256;
                int idx = rel & 255;
                int r = idx >> 3, c = idx & 7;
                const __half* src = (half2nd ? g_xh2 : g_xh1) + (size_t)(n0 + r) * 1024 + k0 + c * 8;
                cp16(st + 2 * GW_T + half2nd * GB_T + r * GROWB + c * 16, src);
            }
        }
        CP_COMMIT();
    };

    load_stage(0, 0);
    load_stage(1, GKC);

    for (int kc = 0; kc < 16; ++kc) {
        if (kc < 15) cp_wait<1>(); else cp_wait<0>();
        __syncthreads();
        if (kc + 2 < 16) load_stage((kc + 2) % 3, (kc + 2) * GKC);
        const uint32_t st = sb + (kc % 3) * GSTAGE;
#pragma unroll
        for (int ks = 0; ks < 4; ++ks) {
            const uint32_t kb = ks * 32;
            const int mat = lane >> 3;
            uint32_t a1[4], a2[4];
            {
                const uint32_t row = vrow0 + (mat & 1) * 8 + (lane & 7);
                const uint32_t ao = row * GROWB + kb + (mat >> 1) * 16;
                ldsm4(a1, st + ao);
                ldsm4(a2, st + GW_T + ao);
            }
            uint32_t b1[2][2], b2[2][2];
            {
                const uint32_t row = bcol0 + (mat >> 1) * 8 + (lane & 7);
                const uint32_t bo = row * GROWB + kb + (mat & 1) * 16;
                uint32_t r[4];
                ldsm4(r, st + 2 * GW_T + bo);
                b1[0][0] = r[0]; b1[0][1] = r[1]; b1[1][0] = r[2]; b1[1][1] = r[3];
                ldsm4(r, st + 2 * GW_T + GB_T + bo);
                b2[0][0] = r[0]; b2[0][1] = r[1]; b2[1][0] = r[2]; b2[1][1] = r[3];
            }
#pragma unroll
            for (int nf = 0; nf < 2; ++nf) {
                mma16816(d0[nf], a1, b1[nf]);
                mma16816(d1[nf], a1, b2[nf]);
                mma16816(d1[nf], a2, b1[nf]);
            }
        }
    }

    // ---- epilogue: combine into sg[32][33], then pointwise ----
    __syncthreads();
    float* sg = (float*)smem;   // [32][33]
    const int r0 = vrow0 + (lane >> 2);
    const int r1 = r0 + 8;
#pragma unroll
    for (int nf = 0; nf < 2; ++nf) {
        const int c = bcol0 + nf * 8 + 2 * (lane & 3);
        sg[r0 * 33 + c]     = d0[nf][0] + d1[nf][0] * 0.0009765625f;
        sg[r0 * 33 + c + 1] = d0[nf][1] + d1[nf][1] * 0.0009765625f;
        sg[r1 * 33 + c]     = d0[nf][2] + d1[nf][2] * 0.0009765625f;
        sg[r1 * 33 + c + 1] = d0[nf][3] + d1[nf][3] * 0.0009765625f;
    }
    __syncthreads();
#pragma unroll
    for (int q = 0; q < 2; ++q) {
        const int idx = tid * 2 + q;       // 0..255
        const int jl = idx >> 5;           // 0..7
        const int bl = idx & 31;
        const int j = j0 + jl;
        const int b = n0 + bl;
        float ig = sigf(sg[(jl)      * 33 + bl] + g_bias[j]);
        float fg = sigf(sg[(8 + jl)  * 33 + bl] + g_bias[512 + j]);
        float gg = tanhf(sg[(16 + jl) * 33 + bl] + g_bias[1024 + j]);
        float og = sigf(sg[(24 + jl) * 33 + bl] + g_bias[1536 + j]);
        float c = fg * g_c[b * 512 + j] + ig * gg;
        g_c[b * 512 + j] = c;
        float h = og * tanhf(c);
        g_hnew[b * 512 + j] = h;
        g_hn1[b * 512 + j] = __float2half_rn(h);
    }
}

// ---------------------------------------------------------------------------
// HMMA approx logits: per CTA 64v x 128b, 128 threads (4 warps, warp 32x64).
// 3-stage ring; epilogue per-column TOP-2 (one thread per column).
#define KC      64
#define ROWB    144
#define WTILEB  (VTILE * ROWB)
#define HTILEB  (128 * ROWB)
#define STAGEB  (WTILEB + HTILEB)
#define SMEM_LOG (3 * STAGEB)

__global__ __launch_bounds__(128, 2) void logits_mma_kernel(const float* __restrict__ bfc) {
    extern __shared__ char smem[];
    const uint32_t sb = smem_u32(smem);
    const int tid = threadIdx.x;
    const int wid = tid >> 5;
    const int lane = tid & 31;
    const int vb = blockIdx.x * VTILE;
    const int vrow0 = (wid & 1) * 32;
    const int brow0 = (wid >> 1) * 64;

    float d0[2][8][4] = {};

    // 1536 granules/stage, 12 per thread
    auto load_stage = [&](int buf, int k0) {
        const uint32_t st = sb + buf * STAGEB;
#pragma unroll
        for (int i = 0; i < 12; ++i) {
            int lin = i * 128 + tid;
            if (lin < 512) {
                int row = lin >> 3, col = lin & 7;
                cp16(st + row * ROWB + col * 16,
                     g_W1 + (size_t)(vb + row) * 512 + k0 + col * 8);
            } else {
                int idx = lin - 512;
                int row = idx >> 3, col = idx & 7;
                cp16(st + WTILEB + row * ROWB + col * 16,
                     g_hn1 + (size_t)row * 512 + k0 + col * 8);
            }
        }
        CP_COMMIT();
    };

    load_stage(0, 0);
    load_stage(1, KC);

    for (int kc = 0; kc < 8; ++kc) {
        if (kc < 7) cp_wait<1>(); else cp_wait<0>();
        __syncthreads();
        if (kc + 2 < 8) load_stage((kc + 2) % 3, (kc + 2) * KC);
        const uint32_t st = sb + (kc % 3) * STAGEB;
#pragma unroll
        for (int ks = 0; ks < 4; ++ks) {
            const uint32_t kb = ks * 32;
            const int mat = lane >> 3;
            uint32_t a1[2][4];
#pragma unroll
            for (int mi = 0; mi < 2; ++mi) {
                const uint32_t row = vrow0 + mi * 16 + (mat & 1) * 8 + (lane & 7);
                ldsm4(a1[mi], st + row * ROWB + kb + (mat >> 1) * 16);
            }
            uint32_t b1[8][2];
#pragma unroll
            for (int j = 0; j < 4; ++j) {
                const uint32_t row = brow0 + j * 16 + (mat >> 1) * 8 + (lane & 7);
                uint32_t r[4];
                ldsm4(r, st + WTILEB + row * ROWB + kb + (mat & 1) * 16);
                b1[2 * j][0] = r[0]; b1[2 * j][1] = r[1];
                b1[2 * j + 1][0] = r[2]; b1[2 * j + 1][1] = r[3];
            }
#pragma unroll
            for (int mi = 0; mi < 2; ++mi)
#pragma unroll
                for (int nf = 0; nf < 8; ++nf)
                    mma16816(d0[mi][nf], a1[mi], b1[nf]);
        }
    }

    // ---- epilogue: logits(+bias) into smem [b][64], per-column top-2 ----
    __syncthreads();
    float* slog = (float*)smem;            // [128][68]
#pragma unroll
    for (int mi = 0; mi < 2; ++mi) {
        const int vloc0 = vrow0 + mi * 16 + (lane >> 2);
        const float bias0 = bfc[vb + vloc0];
        const float bias1 = bfc[vb + vloc0 + 8];
#pragma unroll
        for (int nf = 0; nf < 8; ++nf) {
            const int b0 = brow0 + nf * 8 + 2 * (lane & 3);
            slog[(b0)     * 68 + vloc0]     = d0[mi][nf][0] + bias0;
            slog[(b0 + 1) * 68 + vloc0]     = d0[mi][nf][1] + bias0;
            slog[(b0)     * 68 + vloc0 + 8] = d0[mi][nf][2] + bias1;
            slog[(b0 + 1) * 68 + vloc0 + 8] = d0[mi][nf][3] + bias1;
        }
    }
    __syncthreads();
    {
        const float* col = slog + tid * 68;
        float v1 = col[0]; int i1 = 0;
        float v2 = -INFINITY;
#pragma unroll 8
        for (int v = 1; v < 64; ++v) {
            float x = col[v];
            if (x > v1) { v2 = v1; v1 = x; i1 = v; }
            else if (x > v2) v2 = x;
        }
        const size_t o = (size_t)blockIdx.x * 128 + tid;
        g_p1v[o] = v1;
        g_p1i[o] = vb + i1;
        g_p2v[o] = v2;
    }
}

// ---------------------------------------------------------------------------
// Fixup (as R9) + commit of x/h fp16 splits.
__global__ __launch_bounds__(256) void fixup_kernel(
    const float* __restrict__ Wfc, const float* __restrict__ bfc,
    const float* __restrict__ emb, float* __restrict__ out, int step) {
    __shared__ float sh[512];
    __shared__ float sv[256];
    __shared__ int   si[256];
    __shared__ int   rows[128];
    __shared__ int   blks[16];
    __shared__ int   nrow, nblk;
    const int b = blockIdx.x, t = threadIdx.x;
    const int wid = t >> 5, lane = t & 31;

    for (int k = t; k < 512; k += 256) sh[k] = g_hnew[b * 512 + k];
    if (t == 0) { nrow = 0; nblk = 0; }

    float m = -INFINITY;
    for (int c = t; c < NVBLK2; c += 256) m = fmaxf(m, g_p1v[(size_t)c * 128 + b]);
    sv[t] = m;
    __syncthreads();
    for (int s = 128; s > 0; s >>= 1) {
        if (t < s) sv[t] = fmaxf(sv[t], sv[t + s]);
        __syncthreads();
    }
    const float gmax = sv[0];
    __syncthreads();
    const float thr = gmax - 0.01f * fmaxf(1.0f, fabsf(gmax));

    for (int c = t; c < NVBLK2; c += 256) {
        const size_t o = (size_t)c * 128 + b;
        if (g_p1v[o] >= thr) {
            int p = atomicAdd(&nrow, 1);
            if (p < 128) rows[p] = g_p1i[o];
        }
        if (g_p2v[o] >= thr) {
            int q = atomicAdd(&nblk, 1);
            if (q < 16) blks[q] = c;
        }
    }
    __syncthreads();
    const int nr = min(nrow, 128);
    const int nb = min(nblk, 16);

    float best = -INFINITY;
    int bi = 0x7fffffff;
    for (int ri = wid; ri < nr; ri += 8) {
        const int v = rows[ri];
        const float* w = Wfc + (size_t)v * 512;
        float acc = 0.0f;
#pragma unroll
        for (int j = 0; j < 4; ++j) {
            float4 wv = *(const float4*)(w + lane * 16 + j * 4);
            const float* hh = sh + lane * 16 + j * 4;
            acc += wv.x * hh[0] + wv.y * hh[1] + wv.z * hh[2] + wv.w * hh[3];
        }
#pragma unroll
        for (int o = 16; o; o >>= 1) acc += __shfl_xor_sync(0xffffffffu, acc, o);
        acc += bfc[v];
        if (lane == 0) {
            if (acc > best || (acc == best && v < bi)) { best = acc; bi = v; }
        }
    }
    for (int ci = 0; ci < nb; ++ci) {
        const int c = blks[ci];
        for (int r = wid; r < VTILE; r += 8) {
            const int v = c * VTILE + r;
            const float* w = Wfc + (size_t)v * 512;
            float acc = 0.0f;
#pragma unroll
            for (int j = 0; j < 4; ++j) {
                float4 wv = *(const float4*)(w + lane * 16 + j * 4);
                const float* hh = sh + lane * 16 + j * 4;
                acc += wv.x * hh[0] + wv.y * hh[1] + wv.z * hh[2] + wv.w * hh[3];
            }
#pragma unroll
            for (int o = 16; o; o >>= 1) acc += __shfl_xor_sync(0xffffffffu, acc, o);
            acc += bfc[v];
            if (lane == 0) {
                if (acc > best || (acc == best && v < bi)) { best = acc; bi = v; }
            }
        }
    }
    sv[t] = (lane == 0) ? best : -INFINITY;
    si[t] = (lane == 0) ? bi : 0x7fffffff;
    __syncthreads();
    for (int s = 128; s > 0; s >>= 1) {
        if (t < s) {
            float v = sv[t + s]; int ix = si[t + s];
            if (v > sv[t] || (v == sv[t] && ix < si[t])) { sv[t] = v; si[t] = ix; }
        }
        __syncthreads();
    }
    const int idx = si[0];
    if (t == 0) {
        out[b * TSTEPS + step] = (float)idx;
        out[BATCH * TSTEPS + b * TSTEPS + step] = sv[0];
    }
    for (int k = t; k < 512; k += 256) {
        float x = emb[(size_t)idx * 512 + k];
        __half x1 = __float2half_rn(x);
        g_xh1[b * 1024 + k] = x1;
        g_xh2[b * 1024 + k] = __float2half_rn((x - __half2float(x1)) * 1024.0f);
        float h = sh[k];
        __half h1 = __float2half_rn(h);
        g_xh1[b * 1024 + 512 + k] = h1;
        g_xh2[b * 1024 + 512 + k] = __float2half_rn((h - __half2float(h1)) * 1024.0f);
    }
}

// ---------------------------------------------------------------------------
extern "C" void kernel_launch(void* const* d_in, const int* in_sizes, int n_in,
                              void* d_out, int out_size) {
    const float* features = (const float*)d_in[0];
    const float* emb = (const float*)d_in[2];
    const float* Wih = (const float*)d_in[3];
    const float* Whh = (const float*)d_in[4];
    const float* bih = (const float*)d_in[5];
    const float* bhh = (const float*)d_in[6];
    const float* Wfc = (const float*)d_in[7];
    const float* bfc = (const float*)d_in[8];
    float* out = (float*)d_out;

    cudaFuncSetAttribute(logits_mma_kernel,
                         cudaFuncAttributeMaxDynamicSharedMemorySize, SMEM_LOG);
    cudaFuncSetAttribute(gates_mma_kernel,
                         cudaFuncAttributeMaxDynamicSharedMemorySize, SMEM_G);

    init_kernel<<<BATCH, 256>>>(features);
    wsplit_kernel<<<16000, 256>>>(Wfc);
    wsplit2_kernel<<<2048, 256>>>(Wih, Whh, bih, bhh);
    for (int t = 0; t < TSTEPS; ++t) {
        gates_mma_kernel<<<dim3(64, 4), 128, SMEM_G>>>();
        logits_mma_kernel<<<NVBLK2, 128, SMEM_LOG>>>(bfc);
        fixup_kernel<<<BATCH, 256>>>(Wfc, bfc, emb, out, t);
    }
}